// round 7
// baseline (speedup 1.0000x reference)
#include <cuda_runtime.h>
#include <cuda_bf16.h>
#include <math.h>
#include <stdint.h>

// Problem dims (fixed by the dataset)
#define B_   4
#define N_   512
#define C_   1024
#define HID_ 4096
#define NH_  16
#define D_   64
#define R_   (B_*N_)     // 2048 rows per stream
#define R2_  (2*R_)      // 4096 rows: x-stream and y-stream batched
#define EPS_ 1e-5f

// ---------------- scratch (device globals: no allocation allowed) ----------
__device__ float g_zb[R2_*C_];    // concat(x, y) residual stream
__device__ float g_na[R2_*C_];    // ln1 out (fattn input)
// packed (hi/lo, A-fragment layout) activations
__device__ uint32_t g_obh[R2_*C_/2],  g_obl[R2_*C_/2];    // fattn out -> proj A
__device__ uint32_t g_n2h[R2_*C_/2],  g_n2l[R2_*C_/2];    // ln2 out   -> fc1 A
__device__ uint32_t g_hbh[R2_*HID_/2], g_hbl[R2_*HID_/2]; // gelu out  -> fc2 A
// hi/lo-split weights, packed in mma.m16n8k16 B-fragment layout
__device__ uint32_t g_pwh[C_*C_/2],   g_pwl[C_*C_/2];
__device__ uint32_t g_w1h[C_*HID_/2], g_w1l[C_*HID_/2];
__device__ uint32_t g_w2h[HID_*C_/2], g_w2l[HID_*C_/2];

// ======================= helpers =======================
#define CP_ASYNC16(sm, gp) \
    asm volatile("cp.async.cg.shared.global [%0], [%1], 16;" :: "r"(sm), "l"(gp))
#define CP_COMMIT() asm volatile("cp.async.commit_group;" ::: "memory")
#define CP_WAIT0()  asm volatile("cp.async.wait_group 0;" ::: "memory")
#define CP_WAIT1()  asm volatile("cp.async.wait_group 1;" ::: "memory")

__device__ __forceinline__ uint32_t smem_u32(const void* p) {
    uint32_t a;
    asm("{ .reg .u64 t; cvta.to.shared.u64 t, %1; cvt.u32.u64 %0, t; }" : "=r"(a) : "l"(p));
    return a;
}

__device__ __forceinline__ void splitbf(float x, uint16_t& h, uint16_t& l) {
    __nv_bfloat16 bh = __float2bfloat16_rn(x);
    float r = x - __bfloat162float(bh);
    __nv_bfloat16 bl = __float2bfloat16_rn(r);
    h = __bfloat16_as_ushort(bh);
    l = __bfloat16_as_ushort(bl);
}
__device__ __forceinline__ uint32_t pack2(uint16_t lo16, uint16_t hi16) {
    return (uint32_t)lo16 | ((uint32_t)hi16 << 16);
}
__device__ __forceinline__ void split_pack(float a, float b, uint32_t& ph, uint32_t& pl) {
    uint16_t ha, la, hb2, lb2;
    splitbf(a, ha, la); splitbf(b, hb2, lb2);
    ph = pack2(ha, hb2); pl = pack2(la, lb2);
}

__device__ __forceinline__ void mma_bf16(float* c, const uint32_t* a, const uint32_t* b) {
    asm volatile(
        "mma.sync.aligned.m16n8k16.row.col.f32.bf16.bf16.f32 "
        "{%0,%1,%2,%3}, {%4,%5,%6,%7}, {%8,%9}, {%0,%1,%2,%3};"
        : "+f"(c[0]), "+f"(c[1]), "+f"(c[2]), "+f"(c[3])
        : "r"(a[0]), "r"(a[1]), "r"(a[2]), "r"(a[3]), "r"(b[0]), "r"(b[1]));
}

__device__ __forceinline__ float fast_exp(float x) {
    float tt = fmaxf(x * 1.4426950408889634f, -126.0f);
    float fi = floorf(tt);
    float f = tt - fi;
    float p = 0.0013333558f;
    p = fmaf(p, f, 0.0096181291f);
    p = fmaf(p, f, 0.0555041087f);
    p = fmaf(p, f, 0.2402265070f);
    p = fmaf(p, f, 0.6931471806f);
    p = fmaf(p, f, 1.0f);
    return p * __int_as_float((__float2int_rn(fi) + 127) << 23);
}

// ======================= LayerNorm (raw out, for ln1) =======================
__global__ void ln_kernel(const float* __restrict__ in, float* __restrict__ out,
                          const float* __restrict__ gm, const float* __restrict__ bt,
                          const int* guard) {
    if (guard && !guard[0]) return;
    int row = blockIdx.x;
    const float* x = in + (size_t)row * C_;
    float* y = out + (size_t)row * C_;
    float s = 0.f, ss = 0.f;
    for (int i = threadIdx.x; i < C_; i += 256) {
        float v = x[i];
        s += v; ss += v * v;
    }
    __shared__ float red[16];
    for (int o = 16; o; o >>= 1) {
        s  += __shfl_down_sync(0xffffffffu, s, o);
        ss += __shfl_down_sync(0xffffffffu, ss, o);
    }
    int wid = threadIdx.x >> 5, lid = threadIdx.x & 31;
    if (!lid) { red[wid] = s; red[wid + 8] = ss; }
    __syncthreads();
    float mean, rstd;
    {
        float a = 0.f, c2 = 0.f;
        #pragma unroll
        for (int i = 0; i < 8; i++) { a += red[i]; c2 += red[i + 8]; }
        mean = a * (1.0f / C_);
        float var = c2 * (1.0f / C_) - mean * mean;
        rstd = rsqrtf(var + EPS_);
    }
    for (int i = threadIdx.x; i < C_; i += 256) {
        y[i] = (x[i] - mean) * rstd * gm[i] + bt[i];
    }
}

// ============ LayerNorm -> packed hi/lo A-fragments (for ln2 -> fc1) =========
__global__ void __launch_bounds__(256) lnp_kernel(
    const float* __restrict__ in, uint32_t* __restrict__ outH,
    uint32_t* __restrict__ outL, const float* __restrict__ gm,
    const float* __restrict__ bt, const int* guard)
{
    if (guard && !guard[0]) return;
    extern __shared__ __align__(16) char sml[];
    uint32_t* sh = (uint32_t*)sml;
    uint32_t* sl = (uint32_t*)(sml + 32768);
    const int w = threadIdx.x >> 5, lane = threadIdx.x & 31;

    #pragma unroll
    for (int rr = 0; rr < 2; rr++) {
        const int row = blockIdx.x * 16 + w * 2 + rr;
        const float* x = in + (size_t)row * C_;
        float4 v[8];
        float s = 0.f, ss = 0.f;
        #pragma unroll
        for (int i = 0; i < 8; i++) {
            v[i] = *(const float4*)(x + i * 128 + lane * 4);
            s += v[i].x + v[i].y + v[i].z + v[i].w;
            ss += v[i].x * v[i].x + v[i].y * v[i].y + v[i].z * v[i].z + v[i].w * v[i].w;
        }
        #pragma unroll
        for (int o = 16; o; o >>= 1) {
            s  += __shfl_xor_sync(0xffffffffu, s, o);
            ss += __shfl_xor_sync(0xffffffffu, ss, o);
        }
        float mean = s * (1.0f / C_);
        float rstd = rsqrtf(ss * (1.0f / C_) - mean * mean + EPS_);
        const int ag = row & 7, m8 = (row >> 3) & 1;
        const int kin = (lane & 3) * 4;
        const int tt0 = (kin & 7) >> 1, rk = kin >> 3;
        #pragma unroll
        for (int i = 0; i < 8; i++) {
            int c = i * 128 + lane * 4;
            float4 gv = *(const float4*)(gm + c);
            float4 bv = *(const float4*)(bt + c);
            float n0 = (v[i].x - mean) * rstd * gv.x + bv.x;
            float n1 = (v[i].y - mean) * rstd * gv.y + bv.y;
            float n2 = (v[i].z - mean) * rstd * gv.z + bv.z;
            float n3 = (v[i].w - mean) * rstd * gv.w + bv.w;
            int kt = c >> 4;
            int r = m8 + 2 * rk;
            uint32_t ph, pl;
            split_pack(n0, n1, ph, pl);
            int idx0 = (kt * 32 + ag * 4 + tt0) * 4 + r;
            sh[idx0] = ph; sl[idx0] = pl;
            split_pack(n2, n3, ph, pl);
            int idx1 = (kt * 32 + ag * 4 + tt0 + 1) * 4 + r;
            sh[idx1] = ph; sl[idx1] = pl;
        }
    }
    __syncthreads();
    size_t gbase = (size_t)blockIdx.x * 8192;
    #pragma unroll
    for (int q = 0; q < 8; q++) {
        int i = q * 256 + threadIdx.x;
        *(uint4*)(outH + gbase + (size_t)i * 4) = ((const uint4*)sh)[i];
        *(uint4*)(outL + gbase + (size_t)i * 4) = ((const uint4*)sl)[i];
    }
}

// ========== weight prep: hi/lo split + pack into B-fragment layout =========
__global__ void pack_weight(const float* __restrict__ W, uint32_t* __restrict__ hiP,
                            uint32_t* __restrict__ loP, int K, int N) {
    int warp = threadIdx.x >> 5, lane = threadIdx.x & 31;
    int g = lane >> 2, t = lane & 3;
    int ktiles = K >> 4;
    int tiles = (N >> 3) * ktiles;
    for (int tile = blockIdx.x * 8 + warp; tile < tiles; tile += gridDim.x * 8) {
        int ntg = tile / ktiles, ksg = tile % ktiles;
        int n = ntg * 8 + g;
        #pragma unroll
        for (int reg = 0; reg < 2; reg++) {
            int k = ksg * 16 + 2 * t + reg * 8;
            float x0 = W[(size_t)k * N + n];
            float x1 = W[(size_t)(k + 1) * N + n];
            uint16_t h0, l0, h1, l1;
            splitbf(x0, h0, l0);
            splitbf(x1, h1, l1);
            size_t idx = ((size_t)tile * 32 + lane) * 2 + reg;
            hiP[idx] = pack2(h0, h1);
            loP[idx] = pack2(l0, l1);
        }
    }
}

// ============== bf16-split mma GEMM: 256x128 CTA tile, 8 warps 64x64 ========
// Stage (48KB): AH[0,16K) AL[16K,32K) BH[32K,40K) BL[40K,48K); 3 stages.
#define GM_STAGE 49152
#define GM_SMEM  (3 * GM_STAGE)

template <int EPI>
__global__ void __launch_bounds__(256) gemm_mma(
    const uint32_t* __restrict__ AhiP, const uint32_t* __restrict__ AloP,
    const uint32_t* __restrict__ BhiP, const uint32_t* __restrict__ BloP,
    float* __restrict__ Cout, const float* __restrict__ bias,
    const float* __restrict__ res,
    uint32_t* __restrict__ OutHi, uint32_t* __restrict__ OutLo,
    int M, int Nt, int K, const int* guard)
{
    if (guard && !guard[0]) return;
    extern __shared__ __align__(16) char smc[];
    const int tid = threadIdx.x;
    const int warp = tid >> 5, lane = tid & 31;
    const int g = lane >> 2, t = lane & 3;
    const int wm = warp & 3, wn = warp >> 2;          // 4 m-slots x 2 n-slots
    const int bm = blockIdx.y * 256, bn = blockIdx.x * 128;
    const uint32_t sb = smem_u32(smc);

    const int NIT = K >> 5;
    const int ktiles = K >> 4;
    const int bm16 = bm >> 4, bn8 = bn >> 3;

    // A: 16 mtiles x 2 ktiles x 32 lanes x 16B = 16KB per (hi|lo) per kstep
    auto cpA = [&](int stage, int it) {
        uint32_t dstb = sb + stage * GM_STAGE;
        int kt0 = it * 2;
        #pragma unroll
        for (int q = 0; q < 4; q++) {
            int slot = q * 256 + tid;              // 0..1023
            int mtk = slot >> 5, j = slot & 31;
            int mtl = mtk >> 1, ktl = mtk & 1;
            size_t gidx = (((size_t)(bm16 + mtl) * ktiles + kt0 + ktl) * 32 + j) * 4;
            uint32_t dst = dstb + (uint32_t)slot * 16;
            CP_ASYNC16(dst, AhiP + gidx);
            CP_ASYNC16(dst + 16384u, AloP + gidx);
        }
    };
    // B: 16 ntiles x 2 ktiles x 32 lanes x 8B = 8KB per (hi|lo) per kstep
    auto cpB = [&](int stage, int it) {
        uint32_t dstb = sb + stage * GM_STAGE + 32768u;
        int ksg0 = it * 2;
        #pragma unroll
        for (int q = 0; q < 2; q++) {
            int slot = q * 256 + tid;              // 0..511
            int chunk = slot >> 4, w = slot & 15;  // chunk = ntl*2+ktl
            int ntl = chunk >> 1, ktl = chunk & 1;
            size_t gidx = (((size_t)(bn8 + ntl) * ktiles + ksg0 + ktl) * 64) + (size_t)w * 4;
            uint32_t dst = dstb + (uint32_t)slot * 16;
            CP_ASYNC16(dst, BhiP + gidx);
            CP_ASYNC16(dst + 8192u, BloP + gidx);
        }
    };

    float acc[4][8][4] = {};

    auto compute = [&](int stage) {
        char* base = smc + stage * GM_STAGE;
        #pragma unroll
        for (int ks = 0; ks < 2; ks++) {
            uint32_t ah[4][4], al[4][4];
            #pragma unroll
            for (int mt = 0; mt < 4; mt++) {
                uint32_t off = (uint32_t)(((wm * 4 + mt) * 2 + ks) * 32 + lane) * 16;
                uint4 v = *(const uint4*)(base + off);
                ah[mt][0] = v.x; ah[mt][1] = v.y; ah[mt][2] = v.z; ah[mt][3] = v.w;
                uint4 w = *(const uint4*)(base + 16384 + off);
                al[mt][0] = w.x; al[mt][1] = w.y; al[mt][2] = w.z; al[mt][3] = w.w;
            }
            #pragma unroll
            for (int nt = 0; nt < 8; nt++) {
                uint32_t off = 32768u + (uint32_t)(((wn * 8 + nt) * 2 + ks) * 32 + lane) * 8;
                uint32_t bh[2], bl[2];
                uint2 v = *(const uint2*)(base + off);
                bh[0] = v.x; bh[1] = v.y;
                uint2 w = *(const uint2*)(base + 8192 + off);
                bl[0] = w.x; bl[1] = w.y;
                #pragma unroll
                for (int mt = 0; mt < 4; mt++) {
                    mma_bf16(acc[mt][nt], ah[mt], bh);
                    mma_bf16(acc[mt][nt], ah[mt], bl);
                    mma_bf16(acc[mt][nt], al[mt], bh);
                }
            }
        }
    };

    cpA(0, 0); cpB(0, 0); CP_COMMIT();
    cpA(1, 1); cpB(1, 1); CP_COMMIT();

    int st = 0;
    for (int it = 0; it < NIT; it++) {
        if (it + 1 < NIT) { CP_WAIT1(); } else { CP_WAIT0(); }
        __syncthreads();
        if (it + 2 < NIT) {
            int ns = st + 2; if (ns >= 3) ns -= 3;
            cpA(ns, it + 2); cpB(ns, it + 2); CP_COMMIT();
        }
        compute(st);
        if (++st == 3) st = 0;
    }
    __syncthreads();

    if (EPI == 1) {
        #pragma unroll
        for (int mt = 0; mt < 4; mt++) {
            #pragma unroll
            for (int nt = 0; nt < 8; nt++) {
                int row0 = bm + wm * 64 + mt * 16 + g;
                int col = bn + wn * 64 + nt * 8 + t * 2;
                float2 bv = *(const float2*)&bias[col];
                float v0 = acc[mt][nt][0] + bv.x;
                float v1 = acc[mt][nt][1] + bv.y;
                float v2 = acc[mt][nt][2] + bv.x;
                float v3 = acc[mt][nt][3] + bv.y;
                size_t i0 = (size_t)row0 * Nt + col;
                size_t i1 = (size_t)(row0 + 8) * Nt + col;
                float2 r0 = *(const float2*)&res[i0];
                float2 r1 = *(const float2*)&res[i1];
                *(float2*)&Cout[i0] = make_float2(v0 + r0.x, v1 + r0.y);
                *(float2*)&Cout[i1] = make_float2(v2 + r1.x, v3 + r1.y);
            }
        }
    } else {
        // GELU -> packed hi/lo A-fragments (64KB hi + 64KB lo staged in smem)
        uint32_t* sh = (uint32_t*)smc;
        uint32_t* sl = (uint32_t*)(smc + 65536);
        #pragma unroll
        for (int mt = 0; mt < 4; mt++) {
            #pragma unroll
            for (int nt = 0; nt < 8; nt++) {
                int kl = wn * 64 + nt * 8 + t * 2;   // 0..127 col in tile
                float2 bv = *(const float2*)&bias[bn + kl];
                float v0 = acc[mt][nt][0] + bv.x;
                float v1 = acc[mt][nt][1] + bv.y;
                float v2 = acc[mt][nt][2] + bv.x;
                float v3 = acc[mt][nt][3] + bv.y;
                v0 = 0.5f * v0 * (1.0f + erff(v0 * 0.70710678118654752f));
                v1 = 0.5f * v1 * (1.0f + erff(v1 * 0.70710678118654752f));
                v2 = 0.5f * v2 * (1.0f + erff(v2 * 0.70710678118654752f));
                v3 = 0.5f * v3 * (1.0f + erff(v3 * 0.70710678118654752f));
                int mtl = wm * 4 + mt;               // 0..15
                int ktl = kl >> 4;                   // 0..7
                int tt = (kl & 7) >> 1;              // == t
                int rk = (kl >> 3) & 1;
                int baseI = ((mtl * 8 + ktl) * 32 + g * 4 + tt) * 4;
                uint32_t ph, pl;
                split_pack(v0, v1, ph, pl);
                sh[baseI + 2 * rk] = ph; sl[baseI + 2 * rk] = pl;
                split_pack(v2, v3, ph, pl);
                sh[baseI + 1 + 2 * rk] = ph; sl[baseI + 1 + 2 * rk] = pl;
            }
        }
        __syncthreads();
        const int ktO = Nt >> 4;
        #pragma unroll
        for (int q = 0; q < 16; q++) {
            int i = q * 256 + tid;                   // 0..4095 uint4 slots
            int mtl = i >> 8, jj = i & 255;
            size_t gidx = (((size_t)(bm16 + mtl) * ktO + (bn >> 4)) * 128) + (size_t)jj * 4;
            *(uint4*)(OutHi + gidx) = ((const uint4*)sh)[i];
            *(uint4*)(OutLo + gidx) = ((const uint4*)sl)[i];
        }
    }
}

// ======================= fused flash attention (tensor cores) ===============
// grid (4 q-tiles, 8*NH). batch bb = blockIdx.y>>4 in 0..7 (x:0-3, y:4-7).
// KV batch = bb ^ kvxor (0 = self, 4 = cross between x and y halves).
#define FA_QH 0
#define FA_QL 16384
#define FA_KH 32768
#define FA_KL 49152
#define FA_VH 65536
#define FA_VL 81920
#define FA_SMEM 98304

__global__ void __launch_bounds__(256, 1) fattn_kernel(
    const float* __restrict__ NA, int kvxor,
    uint32_t* __restrict__ Ohi, uint32_t* __restrict__ Olo, const int* guard)
{
    if (guard && !guard[0]) return;
    extern __shared__ __align__(16) char smf[];
    const int tid = threadIdx.x, lane = tid & 31, warp = tid >> 5;
    const int g = lane >> 2, t = lane & 3;
    const int bh = blockIdx.y, b = bh >> 4, h = bh & 15;
    const int n0 = blockIdx.x * 128;
    const float* Qb = NA + (size_t)b * N_ * C_ + h * D_;
    const float* Kb = NA + (size_t)(b ^ kvxor) * N_ * C_ + h * D_;

    // ---- Q -> A-fragments (hi/lo), scaled by 1/8 ----
    {
        const int arow = tid >> 1, hf = tid & 1;
        const float* qp = Qb + (size_t)(n0 + arow) * C_ + hf * 32;
        const int mtile = arow >> 4, ag = arow & 7, arm = (arow >> 3) & 1;
        #pragma unroll
        for (int q4 = 0; q4 < 8; q4++) {
            float4 v = *(const float4*)(qp + q4 * 4);
            float xs[4] = {v.x * 0.125f, v.y * 0.125f, v.z * 0.125f, v.w * 0.125f};
            #pragma unroll
            for (int p = 0; p < 2; p++) {
                int d = hf * 32 + q4 * 4 + 2 * p;
                uint32_t ph, pl;
                split_pack(xs[2 * p], xs[2 * p + 1], ph, pl);
                int kt = d >> 4, kin = d & 15;
                int tt = (kin & 7) >> 1, rk = kin >> 3;
                uint32_t idx = (uint32_t)(((mtile * 4 + kt) * 32 + ag * 4 + tt) * 4 + (arm + 2 * rk));
                *(uint32_t*)(smf + FA_QH + idx * 4) = ph;
                *(uint32_t*)(smf + FA_QL + idx * 4) = pl;
            }
        }
    }
    __syncthreads();

    uint32_t qh[4][4], ql[4][4];
    #pragma unroll
    for (int kt = 0; kt < 4; kt++) {
        uint4 v = *(const uint4*)(smf + FA_QH + (size_t)(((warp * 4 + kt) * 32 + lane) * 4) * 4);
        qh[kt][0] = v.x; qh[kt][1] = v.y; qh[kt][2] = v.z; qh[kt][3] = v.w;
        uint4 w = *(const uint4*)(smf + FA_QL + (size_t)(((warp * 4 + kt) * 32 + lane) * 4) * 4);
        ql[kt][0] = w.x; ql[kt][1] = w.y; ql[kt][2] = w.z; ql[kt][3] = w.w;
    }

    float o[8][4] = {};
    float m0 = -1e30f, m1 = -1e30f, l0 = 0.f, l1 = 0.f;

    for (int ch = 0; ch < 4; ch++) {
        const int s0 = ch * 128;
        __syncthreads();
        // ---- K chunk -> B-frags ----
        {
            const int r = tid >> 1, hf = tid & 1;
            const float* kp = Kb + (size_t)(s0 + r) * C_ + hf * 32;
            const int ntile = r >> 3, kg = r & 7;
            #pragma unroll
            for (int q4 = 0; q4 < 8; q4++) {
                float4 v = *(const float4*)(kp + q4 * 4);
                float xs[4] = {v.x, v.y, v.z, v.w};
                #pragma unroll
                for (int p = 0; p < 2; p++) {
                    int d = hf * 32 + q4 * 4 + 2 * p;
                    uint32_t ph, pl;
                    split_pack(xs[2 * p], xs[2 * p + 1], ph, pl);
                    int kt = d >> 4;
                    int lanef = kg * 4 + ((d & 7) >> 1);
                    int reg = ((d & 15) >= 8) ? 1 : 0;
                    uint32_t idx = (uint32_t)(((ntile * 4 + kt) * 32 + lanef) * 2 + reg);
                    *(uint32_t*)(smf + FA_KH + idx * 4) = ph;
                    *(uint32_t*)(smf + FA_KL + idx * 4) = pl;
                }
            }
        }
        // ---- V chunk -> B-frags (n=d, k=s) ----
        {
            const int sp = tid & 63, dq = tid >> 6;
            const float* vp = Kb + (size_t)(s0 + 2 * sp) * C_ + dq * 16;
            #pragma unroll
            for (int q4 = 0; q4 < 4; q4++) {
                float4 a = *(const float4*)(vp + q4 * 4);
                float4 c = *(const float4*)(vp + C_ + q4 * 4);
                float as[4] = {a.x, a.y, a.z, a.w};
                float cs[4] = {c.x, c.y, c.z, c.w};
                #pragma unroll
                for (int e = 0; e < 4; e++) {
                    int d = dq * 16 + q4 * 4 + e;
                    uint32_t ph, pl;
                    split_pack(as[e], cs[e], ph, pl);
                    int dnt = d >> 3, skt = sp >> 3;
                    int lanef = (d & 7) * 4 + (sp & 3);
                    int reg = (sp >> 2) & 1;
                    uint32_t idx = (uint32_t)(((dnt * 8 + skt) * 32 + lanef) * 2 + reg);
                    *(uint32_t*)(smf + FA_VH + idx * 4) = ph;
                    *(uint32_t*)(smf + FA_VL + idx * 4) = pl;
                }
            }
        }
        __syncthreads();

        // ---- S = Q @ K^T (3-term) ----
        float s[16][4];
        #pragma unroll
        for (int nt = 0; nt < 16; nt++) { s[nt][0] = s[nt][1] = s[nt][2] = s[nt][3] = 0.f; }
        #pragma unroll
        for (int nt = 0; nt < 16; nt++) {
            #pragma unroll
            for (int kt = 0; kt < 4; kt++) {
                uint32_t kh[2], kl[2];
                uint2 a = *(const uint2*)(smf + FA_KH + (size_t)(((nt * 4 + kt) * 32 + lane) * 2) * 4);
                kh[0] = a.x; kh[1] = a.y;
                uint2 c = *(const uint2*)(smf + FA_KL + (size_t)(((nt * 4 + kt) * 32 + lane) * 2) * 4);
                kl[0] = c.x; kl[1] = c.y;
                mma_bf16(s[nt], qh[kt], kh);
                mma_bf16(s[nt], qh[kt], kl);
                mma_bf16(s[nt], ql[kt], kh);
            }
        }

        // ---- online softmax ----
        float cm0 = -1e30f, cm1 = -1e30f;
        #pragma unroll
        for (int nt = 0; nt < 16; nt++) {
            cm0 = fmaxf(cm0, fmaxf(s[nt][0], s[nt][1]));
            cm1 = fmaxf(cm1, fmaxf(s[nt][2], s[nt][3]));
        }
        cm0 = fmaxf(cm0, __shfl_xor_sync(0xffffffffu, cm0, 1));
        cm0 = fmaxf(cm0, __shfl_xor_sync(0xffffffffu, cm0, 2));
        cm1 = fmaxf(cm1, __shfl_xor_sync(0xffffffffu, cm1, 1));
        cm1 = fmaxf(cm1, __shfl_xor_sync(0xffffffffu, cm1, 2));
        float nm0 = fmaxf(m0, cm0), nm1 = fmaxf(m1, cm1);
        float al0 = fast_exp(m0 - nm0), al1 = fast_exp(m1 - nm1);
        m0 = nm0; m1 = nm1;
        #pragma unroll
        for (int dnt = 0; dnt < 8; dnt++) {
            o[dnt][0] *= al0; o[dnt][1] *= al0;
            o[dnt][2] *= al1; o[dnt][3] *= al1;
        }
        float ls0 = 0.f, ls1 = 0.f;

        #pragma unroll
        for (int kt = 0; kt < 8; kt++) {
            float p00 = fast_exp(s[2 * kt][0] - m0);
            float p01 = fast_exp(s[2 * kt][1] - m0);
            float p02 = fast_exp(s[2 * kt][2] - m1);
            float p03 = fast_exp(s[2 * kt][3] - m1);
            float p10 = fast_exp(s[2 * kt + 1][0] - m0);
            float p11 = fast_exp(s[2 * kt + 1][1] - m0);
            float p12 = fast_exp(s[2 * kt + 1][2] - m1);
            float p13 = fast_exp(s[2 * kt + 1][3] - m1);
            ls0 += p00 + p01 + p10 + p11;
            ls1 += p02 + p03 + p12 + p13;
            uint32_t ph[4], pl[4];
            split_pack(p00, p01, ph[0], pl[0]);
            split_pack(p02, p03, ph[1], pl[1]);
            split_pack(p10, p11, ph[2], pl[2]);
            split_pack(p12, p13, ph[3], pl[3]);
            #pragma unroll
            for (int dnt = 0; dnt < 8; dnt++) {
                uint32_t vh[2], vl[2];
                uint2 a = *(const uint2*)(smf + FA_VH + (size_t)(((dnt * 8 + kt) * 32 + lane) * 2) * 4);
                vh[0] = a.x; vh[1] = a.y;
                uint2 c = *(const uint2*)(smf + FA_VL + (size_t)(((dnt * 8 + kt) * 32 + lane) * 2) * 4);
                vl[0] = c.x; vl[1] = c.y;
                mma_bf16(o[dnt], ph, vh);
                mma_bf16(o[dnt], ph, vl);
                mma_bf16(o[dnt], pl, vh);
            }
        }
        ls0 += __shfl_xor_sync(0xffffffffu, ls0, 1);
        ls0 += __shfl_xor_sync(0xffffffffu, ls0, 2);
        ls1 += __shfl_xor_sync(0xffffffffu, ls1, 1);
        ls1 += __shfl_xor_sync(0xffffffffu, ls1, 2);
        l0 = l0 * al0 + ls0;
        l1 = l1 * al1 + ls1;
    }

    // ---- packed epilogue ----
    __syncthreads();
    uint32_t* sh = (uint32_t*)(smf + FA_KH);
    uint32_t* sl = (uint32_t*)(smf + FA_KL);
    float inv0 = 1.0f / l0, inv1 = 1.0f / l1;
    #pragma unroll
    for (int dnt = 0; dnt < 8; dnt++) {
        int kl_ = dnt * 8 + 2 * t;
        int ktl = kl_ >> 4;
        int rk = dnt & 1;
        int baseI = ((warp * 4 + ktl) * 32 + lane) * 4;
        uint32_t ph, pl;
        split_pack(o[dnt][0] * inv0, o[dnt][1] * inv0, ph, pl);
        sh[baseI + 2 * rk] = ph; sl[baseI + 2 * rk] = pl;
        split_pack(o[dnt][2] * inv1, o[dnt][3] * inv1, ph, pl);
        sh[baseI + 1 + 2 * rk] = ph; sl[baseI + 1 + 2 * rk] = pl;
    }
    __syncthreads();
    #pragma unroll
    for (int q = 0; q < 4; q++) {
        int i = q * 256 + tid;
        int mtl = i >> 7, jj = i & 127;
        size_t gidx = (((size_t)(b * 32 + blockIdx.x * 8 + mtl) * 64) + h * 4) * 128 + (size_t)jj * 4;
        *(uint4*)(Ohi + gidx) = ((const uint4*)sh)[i];
        *(uint4*)(Olo + gidx) = ((const uint4*)sl)[i];
    }
}

// ======================= host orchestration =======================
struct Weights {
    const float *n1g, *n1b, *n2g, *n2b, *pw, *pb, *w1, *b1, *w2, *b2;
};
struct Bufs {
    float *zb, *na;
    uint32_t *obh, *obl, *n2h, *n2l, *hbh, *hbl;
    uint32_t *pwh, *pwl, *w1h, *w1l, *w2h, *w2l;
};

// One full transformer block over the batched 4096-row stream.
static void block_batched(float* resbuf, float* outbuf, int kvxor,
                          const Bufs& B, const Weights& W, const int* guard) {
    ln_kernel<<<R2_, 256>>>(resbuf, B.na, W.n1g, W.n1b, guard);
    fattn_kernel<<<dim3(4, 8 * NH_), 256, FA_SMEM>>>(B.na, kvxor, B.obh, B.obl, guard);
    gemm_mma<1><<<dim3(C_ / 128, R2_ / 256), 256, GM_SMEM>>>(
        B.obh, B.obl, B.pwh, B.pwl, outbuf, W.pb, resbuf, nullptr, nullptr,
        R2_, C_, C_, guard);
    lnp_kernel<<<R2_ / 16, 256, 65536>>>(outbuf, B.n2h, B.n2l, W.n2g, W.n2b, guard);
    gemm_mma<2><<<dim3(HID_ / 128, R2_ / 256), 256, GM_SMEM>>>(
        B.n2h, B.n2l, B.w1h, B.w1l, nullptr, W.b1, nullptr, B.hbh, B.hbl,
        R2_, HID_, C_, guard);
    gemm_mma<1><<<dim3(C_ / 128, R2_ / 256), 256, GM_SMEM>>>(
        B.hbh, B.hbl, B.w2h, B.w2l, outbuf, W.b2, outbuf, nullptr, nullptr,
        R2_, C_, HID_, guard);
}

extern "C" void kernel_launch(void* const* d_in, const int* in_sizes, int n_in,
                              void* d_out, int out_size) {
    const float* x   = (const float*)d_in[0];
    const float* y   = (const float*)d_in[1];
    Weights W;
    W.n1g = (const float*)d_in[2];  W.n1b = (const float*)d_in[3];
    W.n2g = (const float*)d_in[4];  W.n2b = (const float*)d_in[5];
    W.pw  = (const float*)d_in[6];  W.pb  = (const float*)d_in[7];
    W.w1  = (const float*)d_in[8];  W.b1  = (const float*)d_in[9];
    W.w2  = (const float*)d_in[10]; W.b2  = (const float*)d_in[11];
    const int* flag = (const int*)d_in[12];
    float* out = (float*)d_out;    // 4096 x 1024 = concat(x1, y1)

    Bufs B;
    cudaGetSymbolAddress((void**)&B.zb, g_zb);
    cudaGetSymbolAddress((void**)&B.na, g_na);
    cudaGetSymbolAddress((void**)&B.obh, g_obh);
    cudaGetSymbolAddress((void**)&B.obl, g_obl);
    cudaGetSymbolAddress((void**)&B.n2h, g_n2h);
    cudaGetSymbolAddress((void**)&B.n2l, g_n2l);
    cudaGetSymbolAddress((void**)&B.hbh, g_hbh);
    cudaGetSymbolAddress((void**)&B.hbl, g_hbl);
    cudaGetSymbolAddress((void**)&B.pwh, g_pwh);
    cudaGetSymbolAddress((void**)&B.pwl, g_pwl);
    cudaGetSymbolAddress((void**)&B.w1h, g_w1h);
    cudaGetSymbolAddress((void**)&B.w1l, g_w1l);
    cudaGetSymbolAddress((void**)&B.w2h, g_w2h);
    cudaGetSymbolAddress((void**)&B.w2l, g_w2l);

    cudaFuncSetAttribute(gemm_mma<1>, cudaFuncAttributeMaxDynamicSharedMemorySize, GM_SMEM);
    cudaFuncSetAttribute(gemm_mma<2>, cudaFuncAttributeMaxDynamicSharedMemorySize, GM_SMEM);
    cudaFuncSetAttribute(fattn_kernel, cudaFuncAttributeMaxDynamicSharedMemorySize, FA_SMEM);
    cudaFuncSetAttribute(lnp_kernel, cudaFuncAttributeMaxDynamicSharedMemorySize, 65536);

    // weight prep (runs every launch; ~25us)
    pack_weight<<<512, 256>>>(W.pw, B.pwh, B.pwl, C_, C_);
    pack_weight<<<512, 256>>>(W.w1, B.w1h, B.w1l, C_, HID_);
    pack_weight<<<512, 256>>>(W.w2, B.w2h, B.w2l, HID_, C_);

    const size_t bytes = (size_t)R_ * C_ * sizeof(float);
    cudaMemcpyAsync(B.zb, x, bytes, cudaMemcpyDeviceToDevice);
    cudaMemcpyAsync(B.zb + (size_t)R_ * C_, y, bytes, cudaMemcpyDeviceToDevice);

    // x and y self-chains batched as 8 "batches" (x:0-3, y:4-7). Only the
    // FINAL iteration's cross block is live: 4 gated self blocks, then one
    // cross block (kv from opposite half).
    for (int it = 0; it < 4; it++) {
        block_batched(B.zb, B.zb, 0, B, W, flag);
    }
    block_batched(B.zb, out, 4, B, W, nullptr);
}

// round 8
// speedup vs baseline: 1.1596x; 1.1596x over previous
#include <cuda_runtime.h>
#include <cuda_bf16.h>
#include <math.h>
#include <stdint.h>

// Problem dims (fixed by the dataset)
#define B_   4
#define N_   512
#define C_   1024
#define HID_ 4096
#define NH_  16
#define D_   64
#define R_   (B_*N_)     // 2048 rows per stream
#define R2_  (2*R_)      // 4096 rows: x-stream and y-stream batched
#define EPS_ 1e-5f

// ---------------- scratch (device globals: no allocation allowed) ----------
__device__ float g_zb[R2_*C_];    // concat(x, y) residual stream
__device__ float2 g_st[R2_];      // per-row LN1 stats (mean, rstd)
// packed (hi/lo, A-fragment layout) activations
__device__ uint32_t g_obh[R2_*C_/2],  g_obl[R2_*C_/2];    // fattn out -> proj A
__device__ uint32_t g_n2h[R2_*C_/2],  g_n2l[R2_*C_/2];    // ln2 out   -> fc1 A
__device__ uint32_t g_hbh[R2_*HID_/2], g_hbl[R2_*HID_/2]; // gelu out  -> fc2 A
// hi/lo-split weights, packed in mma.m16n8k16 B-fragment layout
__device__ uint32_t g_pwh[C_*C_/2],   g_pwl[C_*C_/2];
__device__ uint32_t g_w1h[C_*HID_/2], g_w1l[C_*HID_/2];
__device__ uint32_t g_w2h[HID_*C_/2], g_w2l[HID_*C_/2];

// ======================= helpers =======================
#define CP_ASYNC16(sm, gp) \
    asm volatile("cp.async.cg.shared.global [%0], [%1], 16;" :: "r"(sm), "l"(gp))
#define CP_COMMIT() asm volatile("cp.async.commit_group;" ::: "memory")
#define CP_WAIT0()  asm volatile("cp.async.wait_group 0;" ::: "memory")
#define CP_WAIT1()  asm volatile("cp.async.wait_group 1;" ::: "memory")

__device__ __forceinline__ uint32_t smem_u32(const void* p) {
    uint32_t a;
    asm("{ .reg .u64 t; cvta.to.shared.u64 t, %1; cvt.u32.u64 %0, t; }" : "=r"(a) : "l"(p));
    return a;
}

__device__ __forceinline__ void splitbf(float x, uint16_t& h, uint16_t& l) {
    __nv_bfloat16 bh = __float2bfloat16_rn(x);
    float r = x - __bfloat162float(bh);
    __nv_bfloat16 bl = __float2bfloat16_rn(r);
    h = __bfloat16_as_ushort(bh);
    l = __bfloat16_as_ushort(bl);
}
__device__ __forceinline__ uint32_t pack2(uint16_t lo16, uint16_t hi16) {
    return (uint32_t)lo16 | ((uint32_t)hi16 << 16);
}
__device__ __forceinline__ void split_pack(float a, float b, uint32_t& ph, uint32_t& pl) {
    uint16_t ha, la, hb2, lb2;
    splitbf(a, ha, la); splitbf(b, hb2, lb2);
    ph = pack2(ha, hb2); pl = pack2(la, lb2);
}

__device__ __forceinline__ void mma_bf16(float* c, const uint32_t* a, const uint32_t* b) {
    asm volatile(
        "mma.sync.aligned.m16n8k16.row.col.f32.bf16.bf16.f32 "
        "{%0,%1,%2,%3}, {%4,%5,%6,%7}, {%8,%9}, {%0,%1,%2,%3};"
        : "+f"(c[0]), "+f"(c[1]), "+f"(c[2]), "+f"(c[3])
        : "r"(a[0]), "r"(a[1]), "r"(a[2]), "r"(a[3]), "r"(b[0]), "r"(b[1]));
}

__device__ __forceinline__ float fast_exp(float x) {
    float tt = fmaxf(x * 1.4426950408889634f, -126.0f);
    float fi = floorf(tt);
    float f = tt - fi;
    float p = 0.0013333558f;
    p = fmaf(p, f, 0.0096181291f);
    p = fmaf(p, f, 0.0555041087f);
    p = fmaf(p, f, 0.2402265070f);
    p = fmaf(p, f, 0.6931471806f);
    p = fmaf(p, f, 1.0f);
    return p * __int_as_float((__float2int_rn(fi) + 127) << 23);
}

// =============== LN1 row stats: mean + rstd only (one warp per row) =========
__global__ void __launch_bounds__(256) ln_stats(const float* __restrict__ in,
                                                float2* __restrict__ st,
                                                const int* guard) {
    if (guard && !guard[0]) return;
    int row = blockIdx.x * 8 + (threadIdx.x >> 5);
    int lane = threadIdx.x & 31;
    const float* x = in + (size_t)row * C_;
    float s = 0.f, ss = 0.f;
    #pragma unroll
    for (int i = 0; i < 8; i++) {
        float4 v = *(const float4*)(x + i * 128 + lane * 4);
        s += v.x + v.y + v.z + v.w;
        ss += v.x * v.x + v.y * v.y + v.z * v.z + v.w * v.w;
    }
    #pragma unroll
    for (int o = 16; o; o >>= 1) {
        s  += __shfl_xor_sync(0xffffffffu, s, o);
        ss += __shfl_xor_sync(0xffffffffu, ss, o);
    }
    if (lane == 0) {
        float mean = s * (1.0f / C_);
        float rstd = rsqrtf(ss * (1.0f / C_) - mean * mean + EPS_);
        st[row] = make_float2(mean, rstd);
    }
}

// ============ LayerNorm -> packed hi/lo A-fragments (for ln2 -> fc1) =========
__global__ void __launch_bounds__(256) lnp_kernel(
    const float* __restrict__ in, uint32_t* __restrict__ outH,
    uint32_t* __restrict__ outL, const float* __restrict__ gm,
    const float* __restrict__ bt, const int* guard)
{
    if (guard && !guard[0]) return;
    extern __shared__ __align__(16) char sml[];
    uint32_t* sh = (uint32_t*)sml;
    uint32_t* sl = (uint32_t*)(sml + 32768);
    const int w = threadIdx.x >> 5, lane = threadIdx.x & 31;

    #pragma unroll
    for (int rr = 0; rr < 2; rr++) {
        const int row = blockIdx.x * 16 + w * 2 + rr;
        const float* x = in + (size_t)row * C_;
        float4 v[8];
        float s = 0.f, ss = 0.f;
        #pragma unroll
        for (int i = 0; i < 8; i++) {
            v[i] = *(const float4*)(x + i * 128 + lane * 4);
            s += v[i].x + v[i].y + v[i].z + v[i].w;
            ss += v[i].x * v[i].x + v[i].y * v[i].y + v[i].z * v[i].z + v[i].w * v[i].w;
        }
        #pragma unroll
        for (int o = 16; o; o >>= 1) {
            s  += __shfl_xor_sync(0xffffffffu, s, o);
            ss += __shfl_xor_sync(0xffffffffu, ss, o);
        }
        float mean = s * (1.0f / C_);
        float rstd = rsqrtf(ss * (1.0f / C_) - mean * mean + EPS_);
        const int ag = row & 7, m8 = (row >> 3) & 1;
        const int kin = (lane & 3) * 4;
        const int tt0 = (kin & 7) >> 1, rk = kin >> 3;
        #pragma unroll
        for (int i = 0; i < 8; i++) {
            int c = i * 128 + lane * 4;
            float4 gv = *(const float4*)(gm + c);
            float4 bv = *(const float4*)(bt + c);
            float n0 = (v[i].x - mean) * rstd * gv.x + bv.x;
            float n1 = (v[i].y - mean) * rstd * gv.y + bv.y;
            float n2 = (v[i].z - mean) * rstd * gv.z + bv.z;
            float n3 = (v[i].w - mean) * rstd * gv.w + bv.w;
            int kt = c >> 4;
            int r = m8 + 2 * rk;
            uint32_t ph, pl;
            split_pack(n0, n1, ph, pl);
            int idx0 = (kt * 32 + ag * 4 + tt0) * 4 + r;
            sh[idx0] = ph; sl[idx0] = pl;
            split_pack(n2, n3, ph, pl);
            int idx1 = (kt * 32 + ag * 4 + tt0 + 1) * 4 + r;
            sh[idx1] = ph; sl[idx1] = pl;
        }
    }
    __syncthreads();
    size_t gbase = (size_t)blockIdx.x * 8192;
    #pragma unroll
    for (int q = 0; q < 8; q++) {
        int i = q * 256 + threadIdx.x;
        *(uint4*)(outH + gbase + (size_t)i * 4) = ((const uint4*)sh)[i];
        *(uint4*)(outL + gbase + (size_t)i * 4) = ((const uint4*)sl)[i];
    }
}

// ========== weight prep: hi/lo split + pack into B-fragment layout =========
__global__ void pack_weight(const float* __restrict__ W, uint32_t* __restrict__ hiP,
                            uint32_t* __restrict__ loP, int K, int N) {
    int warp = threadIdx.x >> 5, lane = threadIdx.x & 31;
    int g = lane >> 2, t = lane & 3;
    int ktiles = K >> 4;
    int tiles = (N >> 3) * ktiles;
    for (int tile = blockIdx.x * 8 + warp; tile < tiles; tile += gridDim.x * 8) {
        int ntg = tile / ktiles, ksg = tile % ktiles;
        int n = ntg * 8 + g;
        #pragma unroll
        for (int reg = 0; reg < 2; reg++) {
            int k = ksg * 16 + 2 * t + reg * 8;
            float x0 = W[(size_t)k * N + n];
            float x1 = W[(size_t)(k + 1) * N + n];
            uint16_t h0, l0, h1, l1;
            splitbf(x0, h0, l0);
            splitbf(x1, h1, l1);
            size_t idx = ((size_t)tile * 32 + lane) * 2 + reg;
            hiP[idx] = pack2(h0, h1);
            loP[idx] = pack2(l0, l1);
        }
    }
}

// ======================= bf16-split mma GEMM (packed A + packed B) ==========
// 128x128 CTA tile, K-step 32, 3-stage cp.async pipeline, 8 warps (2M x 4N).
// __launch_bounds__(256, 2): 2 CTAs/SM (96KB x 2 smem, <=128 regs) ->
// proj/fc2 grids (256 CTAs) fit one wave on 148 SMs.
#define GM_STAGE 32768
#define GM_SMEM  (3 * GM_STAGE)

template <int EPI>
__global__ void __launch_bounds__(256, 2) gemm_mma(
    const uint32_t* __restrict__ AhiP, const uint32_t* __restrict__ AloP,
    const uint32_t* __restrict__ BhiP, const uint32_t* __restrict__ BloP,
    float* __restrict__ Cout, const float* __restrict__ bias,
    const float* __restrict__ res,
    uint32_t* __restrict__ OutHi, uint32_t* __restrict__ OutLo,
    int M, int Nt, int K, const int* guard)
{
    if (guard && !guard[0]) return;
    extern __shared__ __align__(16) char smc[];
    const int tid = threadIdx.x;
    const int warp = tid >> 5, lane = tid & 31;
    const int g = lane >> 2, t = lane & 3;
    const int wm = warp & 1, wn = warp >> 1;
    const int bm = blockIdx.y * 128, bn = blockIdx.x * 128;
    const uint32_t sb = smem_u32(smc);

    const int NIT = K >> 5;
    const int ktiles = K >> 4;
    const int bm16 = bm >> 4, bn8 = bn >> 3;

    auto cpA = [&](int stage, int it) {
        uint32_t dstb = sb + stage * GM_STAGE;
        int kt0 = it * 2;
        #pragma unroll
        for (int q = 0; q < 2; q++) {
            int chunk = q * 256 + tid;
            int mtk = chunk >> 5, j = chunk & 31;
            int mtl = mtk >> 1, ktl = mtk & 1;
            size_t gidx = (((size_t)(bm16 + mtl) * ktiles + kt0 + ktl) * 32 + j) * 4;
            uint32_t dst = dstb + (uint32_t)(mtk * 512 + j * 16);
            CP_ASYNC16(dst, AhiP + gidx);
            CP_ASYNC16(dst + 8192u, AloP + gidx);
        }
    };
    auto cpB = [&](int stage, int it) {
        uint32_t dstb = sb + stage * GM_STAGE + 16384;
        int ksg0 = it * 2;
        #pragma unroll
        for (int q = 0; q < 2; q++) {
            int i = q * 256 + tid;
            int nt = i >> 5, j = i & 31;
            size_t srcoff = (((size_t)(bn8 + nt) * ktiles + ksg0) * 64 + (size_t)j * 4);
            uint32_t dst = dstb + (uint32_t)(nt * 512 + j * 16);
            CP_ASYNC16(dst, BhiP + srcoff);
            CP_ASYNC16(dst + 8192u, BloP + srcoff);
        }
    };

    float acc[4][4][4] = {};

    auto compute = [&](int stage) {
        char* base = smc + stage * GM_STAGE;
        #pragma unroll
        for (int ks = 0; ks < 2; ks++) {
            uint32_t ah[4][4], al[4][4], bh[4][2], bl[4][2];
            #pragma unroll
            for (int mt = 0; mt < 4; mt++) {
                uint32_t off = (uint32_t)(((wm * 4 + mt) * 2 + ks) * 32 + lane) * 16;
                uint4 v = *(const uint4*)(base + off);
                ah[mt][0] = v.x; ah[mt][1] = v.y; ah[mt][2] = v.z; ah[mt][3] = v.w;
                uint4 w = *(const uint4*)(base + 8192 + off);
                al[mt][0] = w.x; al[mt][1] = w.y; al[mt][2] = w.z; al[mt][3] = w.w;
            }
            #pragma unroll
            for (int nt = 0; nt < 4; nt++) {
                uint32_t off = 16384u + (uint32_t)(((wn * 4 + nt) * 2 + ks) * 32 + lane) * 8;
                uint2 v = *(const uint2*)(base + off);
                bh[nt][0] = v.x; bh[nt][1] = v.y;
                uint2 w = *(const uint2*)(base + 8192 + off);
                bl[nt][0] = w.x; bl[nt][1] = w.y;
            }
            #pragma unroll
            for (int mt = 0; mt < 4; mt++)
                #pragma unroll
                for (int nt = 0; nt < 4; nt++) {
                    mma_bf16(acc[mt][nt], ah[mt], bh[nt]);
                    mma_bf16(acc[mt][nt], ah[mt], bl[nt]);
                    mma_bf16(acc[mt][nt], al[mt], bh[nt]);
                }
        }
    };

    cpA(0, 0); cpB(0, 0); CP_COMMIT();
    cpA(1, 1); cpB(1, 1); CP_COMMIT();

    int st = 0;
    for (int it = 0; it < NIT; it++) {
        if (it + 1 < NIT) { CP_WAIT1(); } else { CP_WAIT0(); }
        __syncthreads();
        if (it + 2 < NIT) {
            int ns = st + 2; if (ns >= 3) ns -= 3;
            cpA(ns, it + 2); cpB(ns, it + 2); CP_COMMIT();
        }
        compute(st);
        if (++st == 3) st = 0;
    }
    __syncthreads();

    if (EPI == 1) {
        #pragma unroll
        for (int mt = 0; mt < 4; mt++) {
            #pragma unroll
            for (int nt = 0; nt < 4; nt++) {
                int row0 = bm + wm * 64 + mt * 16 + g;
                int col = bn + wn * 32 + nt * 8 + t * 2;
                float2 bv = *(const float2*)&bias[col];
                float v0 = acc[mt][nt][0] + bv.x;
                float v1 = acc[mt][nt][1] + bv.y;
                float v2 = acc[mt][nt][2] + bv.x;
                float v3 = acc[mt][nt][3] + bv.y;
                size_t i0 = (size_t)row0 * Nt + col;
                size_t i1 = (size_t)(row0 + 8) * Nt + col;
                float2 r0 = *(const float2*)&res[i0];
                float2 r1 = *(const float2*)&res[i1];
                *(float2*)&Cout[i0] = make_float2(v0 + r0.x, v1 + r0.y);
                *(float2*)&Cout[i1] = make_float2(v2 + r1.x, v3 + r1.y);
            }
        }
    } else {
        uint32_t* sh = (uint32_t*)smc;
        uint32_t* sl = (uint32_t*)(smc + 32768);
        #pragma unroll
        for (int mt = 0; mt < 4; mt++) {
            #pragma unroll
            for (int nt = 0; nt < 4; nt++) {
                int kl = wn * 32 + nt * 8 + t * 2;
                float2 bv = *(const float2*)&bias[bn + kl];
                float v0 = acc[mt][nt][0] + bv.x;
                float v1 = acc[mt][nt][1] + bv.y;
                float v2 = acc[mt][nt][2] + bv.x;
                float v3 = acc[mt][nt][3] + bv.y;
                v0 = 0.5f * v0 * (1.0f + erff(v0 * 0.70710678118654752f));
                v1 = 0.5f * v1 * (1.0f + erff(v1 * 0.70710678118654752f));
                v2 = 0.5f * v2 * (1.0f + erff(v2 * 0.70710678118654752f));
                v3 = 0.5f * v3 * (1.0f + erff(v3 * 0.70710678118654752f));
                int mtl = wm * 4 + mt;
                int ktl = kl >> 4;
                int tt = (kl & 7) >> 1;
                int rk = (kl >> 3) & 1;
                int baseI = ((mtl * 8 + ktl) * 32 + g * 4 + tt) * 4;
                uint32_t ph, pl;
                split_pack(v0, v1, ph, pl);
                sh[baseI + 2 * rk] = ph; sl[baseI + 2 * rk] = pl;
                split_pack(v2, v3, ph, pl);
                sh[baseI + 1 + 2 * rk] = ph; sl[baseI + 1 + 2 * rk] = pl;
            }
        }
        __syncthreads();
        const int ktO = Nt >> 4;
        #pragma unroll
        for (int q = 0; q < 8; q++) {
            int i = q * 256 + tid;
            int mtl = i >> 8, jj = i & 255;
            size_t gidx = (((size_t)(bm16 + mtl) * ktO + (bn >> 4)) * 128) + (size_t)jj * 4;
            *(uint4*)(OutHi + gidx) = ((const uint4*)sh)[i];
            *(uint4*)(OutLo + gidx) = ((const uint4*)sl)[i];
        }
    }
}

// ======================= fused flash attention (LN1 fused in loads) =========
// grid (4 q-tiles, 8*NH). batch b = blockIdx.y>>4 in 0..7 (x:0-3, y:4-7).
// KV batch = b ^ kvxor. LN1 applied on the fly: (z - mean)*rstd*gamma + beta.
#define FA_QH 0
#define FA_QL 16384
#define FA_KH 32768
#define FA_KL 49152
#define FA_VH 65536
#define FA_VL 81920
#define FA_GB 98304
#define FA_SMEM (98304 + 512)

__global__ void __launch_bounds__(256, 1) fattn_kernel(
    const float* __restrict__ Z, const float2* __restrict__ st,
    const float* __restrict__ gm, const float* __restrict__ bt,
    int kvxor, uint32_t* __restrict__ Ohi, uint32_t* __restrict__ Olo,
    const int* guard)
{
    if (guard && !guard[0]) return;
    extern __shared__ __align__(16) char smf[];
    const int tid = threadIdx.x, lane = tid & 31, warp = tid >> 5;
    const int g = lane >> 2, t = lane & 3;
    const int bh = blockIdx.y, b = bh >> 4, h = bh & 15;
    const int bk = b ^ kvxor;
    const int n0 = blockIdx.x * 128;
    float* sg = (float*)(smf + FA_GB);        // gamma slice [64]
    float* sbv = sg + 64;                     // beta slice  [64]
    if (tid < 64) {
        sg[tid]  = gm[h * D_ + tid];
        sbv[tid] = bt[h * D_ + tid];
    }
    __syncthreads();

    // ---- Q -> A-fragments (hi/lo), LN applied, scaled by 1/8 ----
    {
        const int arow = tid >> 1, hf = tid & 1;
        const int grow = b * N_ + n0 + arow;
        const float* qp = Z + (size_t)grow * C_ + h * D_ + hf * 32;
        const float2 sq = st[grow];
        const int mtile = arow >> 4, ag = arow & 7, arm = (arow >> 3) & 1;
        #pragma unroll
        for (int q4 = 0; q4 < 8; q4++) {
            float4 v = *(const float4*)(qp + q4 * 4);
            float4 gv = *(const float4*)(sg + hf * 32 + q4 * 4);
            float4 bv = *(const float4*)(sbv + hf * 32 + q4 * 4);
            float xs[4] = {
                (fmaf((v.x - sq.x) * sq.y, gv.x, bv.x)) * 0.125f,
                (fmaf((v.y - sq.x) * sq.y, gv.y, bv.y)) * 0.125f,
                (fmaf((v.z - sq.x) * sq.y, gv.z, bv.z)) * 0.125f,
                (fmaf((v.w - sq.x) * sq.y, gv.w, bv.w)) * 0.125f };
            #pragma unroll
            for (int p = 0; p < 2; p++) {
                int d = hf * 32 + q4 * 4 + 2 * p;
                uint32_t ph, pl;
                split_pack(xs[2 * p], xs[2 * p + 1], ph, pl);
                int kt = d >> 4, kin = d & 15;
                int tt = (kin & 7) >> 1, rk = kin >> 3;
                uint32_t idx = (uint32_t)(((mtile * 4 + kt) * 32 + ag * 4 + tt) * 4 + (arm + 2 * rk));
                *(uint32_t*)(smf + FA_QH + idx * 4) = ph;
                *(uint32_t*)(smf + FA_QL + idx * 4) = pl;
            }
        }
    }
    __syncthreads();

    uint32_t qh[4][4], ql[4][4];
    #pragma unroll
    for (int kt = 0; kt < 4; kt++) {
        uint4 v = *(const uint4*)(smf + FA_QH + (size_t)(((warp * 4 + kt) * 32 + lane) * 4) * 4);
        qh[kt][0] = v.x; qh[kt][1] = v.y; qh[kt][2] = v.z; qh[kt][3] = v.w;
        uint4 w = *(const uint4*)(smf + FA_QL + (size_t)(((warp * 4 + kt) * 32 + lane) * 4) * 4);
        ql[kt][0] = w.x; ql[kt][1] = w.y; ql[kt][2] = w.z; ql[kt][3] = w.w;
    }

    float o[8][4] = {};
    float m0 = -1e30f, m1 = -1e30f, l0 = 0.f, l1 = 0.f;

    for (int ch = 0; ch < 4; ch++) {
        const int s0 = ch * 128;
        __syncthreads();
        // ---- K chunk -> B-frags (LN applied) ----
        {
            const int r = tid >> 1, hf = tid & 1;
            const int grow = bk * N_ + s0 + r;
            const float* kp = Z + (size_t)grow * C_ + h * D_ + hf * 32;
            const float2 sk = st[grow];
            const int ntile = r >> 3, kg = r & 7;
            #pragma unroll
            for (int q4 = 0; q4 < 8; q4++) {
                float4 v = *(const float4*)(kp + q4 * 4);
                float4 gv = *(const float4*)(sg + hf * 32 + q4 * 4);
                float4 bv = *(const float4*)(sbv + hf * 32 + q4 * 4);
                float xs[4] = {
                    fmaf((v.x - sk.x) * sk.y, gv.x, bv.x),
                    fmaf((v.y - sk.x) * sk.y, gv.y, bv.y),
                    fmaf((v.z - sk.x) * sk.y, gv.z, bv.z),
                    fmaf((v.w - sk.x) * sk.y, gv.w, bv.w) };
                #pragma unroll
                for (int p = 0; p < 2; p++) {
                    int d = hf * 32 + q4 * 4 + 2 * p;
                    uint32_t ph, pl;
                    split_pack(xs[2 * p], xs[2 * p + 1], ph, pl);
                    int kt = d >> 4;
                    int lanef = kg * 4 + ((d & 7) >> 1);
                    int reg = ((d & 15) >= 8) ? 1 : 0;
                    uint32_t idx = (uint32_t)(((ntile * 4 + kt) * 32 + lanef) * 2 + reg);
                    *(uint32_t*)(smf + FA_KH + idx * 4) = ph;
                    *(uint32_t*)(smf + FA_KL + idx * 4) = pl;
                }
            }
        }
        // ---- V chunk -> B-frags (n=d, k=s; LN applied) ----
        {
            const int sp = tid & 63, dq = tid >> 6;
            const int grow = bk * N_ + s0 + 2 * sp;
            const float* vp = Z + (size_t)grow * C_ + h * D_ + dq * 16;
            const float2 sa = st[grow];
            const float2 sc = st[grow + 1];
            #pragma unroll
            for (int q4 = 0; q4 < 4; q4++) {
                float4 a = *(const float4*)(vp + q4 * 4);
                float4 c = *(const float4*)(vp + C_ + q4 * 4);
                float as[4] = {a.x, a.y, a.z, a.w};
                float cs[4] = {c.x, c.y, c.z, c.w};
                #pragma unroll
                for (int e = 0; e < 4; e++) {
                    int d = dq * 16 + q4 * 4 + e;
                    float gvv = sg[d], bvv = sbv[d];
                    float av = fmaf((as[e] - sa.x) * sa.y, gvv, bvv);
                    float cv = fmaf((cs[e] - sc.x) * sc.y, gvv, bvv);
                    uint32_t ph, pl;
                    split_pack(av, cv, ph, pl);
                    int dnt = d >> 3, skt = sp >> 3;
                    int lanef = (d & 7) * 4 + (sp & 3);
                    int reg = (sp >> 2) & 1;
                    uint32_t idx = (uint32_t)(((dnt * 8 + skt) * 32 + lanef) * 2 + reg);
                    *(uint32_t*)(smf + FA_VH + idx * 4) = ph;
                    *(uint32_t*)(smf + FA_VL + idx * 4) = pl;
                }
            }
        }
        __syncthreads();

        // ---- S = Q @ K^T (3-term) ----
        float s[16][4];
        #pragma unroll
        for (int nt = 0; nt < 16; nt++) { s[nt][0] = s[nt][1] = s[nt][2] = s[nt][3] = 0.f; }
        #pragma unroll
        for (int nt = 0; nt < 16; nt++) {
            #pragma unroll
            for (int kt = 0; kt < 4; kt++) {
                uint32_t kh[2], kl[2];
                uint2 a = *(const uint2*)(smf + FA_KH + (size_t)(((nt * 4 + kt) * 32 + lane) * 2) * 4);
                kh[0] = a.x; kh[1] = a.y;
                uint2 c = *(const uint2*)(smf + FA_KL + (size_t)(((nt * 4 + kt) * 32 + lane) * 2) * 4);
                kl[0] = c.x; kl[1] = c.y;
                mma_bf16(s[nt], qh[kt], kh);
                mma_bf16(s[nt], qh[kt], kl);
                mma_bf16(s[nt], ql[kt], kh);
            }
        }

        // ---- online softmax ----
        float cm0 = -1e30f, cm1 = -1e30f;
        #pragma unroll
        for (int nt = 0; nt < 16; nt++) {
            cm0 = fmaxf(cm0, fmaxf(s[nt][0], s[nt][1]));
            cm1 = fmaxf(cm1, fmaxf(s[nt][2], s[nt][3]));
        }
        cm0 = fmaxf(cm0, __shfl_xor_sync(0xffffffffu, cm0, 1));
        cm0 = fmaxf(cm0, __shfl_xor_sync(0xffffffffu, cm0, 2));
        cm1 = fmaxf(cm1, __shfl_xor_sync(0xffffffffu, cm1, 1));
        cm1 = fmaxf(cm1, __shfl_xor_sync(0xffffffffu, cm1, 2));
        float nm0 = fmaxf(m0, cm0), nm1 = fmaxf(m1, cm1);
        float al0 = fast_exp(m0 - nm0), al1 = fast_exp(m1 - nm1);
        m0 = nm0; m1 = nm1;
        #pragma unroll
        for (int dnt = 0; dnt < 8; dnt++) {
            o[dnt][0] *= al0; o[dnt][1] *= al0;
            o[dnt][2] *= al1; o[dnt][3] *= al1;
        }
        float ls0 = 0.f, ls1 = 0.f;

        #pragma unroll
        for (int kt = 0; kt < 8; kt++) {
            float p00 = fast_exp(s[2 * kt][0] - m0);
            float p01 = fast_exp(s[2 * kt][1] - m0);
            float p02 = fast_exp(s[2 * kt][2] - m1);
            float p03 = fast_exp(s[2 * kt][3] - m1);
            float p10 = fast_exp(s[2 * kt + 1][0] - m0);
            float p11 = fast_exp(s[2 * kt + 1][1] - m0);
            float p12 = fast_exp(s[2 * kt + 1][2] - m1);
            float p13 = fast_exp(s[2 * kt + 1][3] - m1);
            ls0 += p00 + p01 + p10 + p11;
            ls1 += p02 + p03 + p12 + p13;
            uint32_t ph[4], pl[4];
            split_pack(p00, p01, ph[0], pl[0]);
            split_pack(p02, p03, ph[1], pl[1]);
            split_pack(p10, p11, ph[2], pl[2]);
            split_pack(p12, p13, ph[3], pl[3]);
            #pragma unroll
            for (int dnt = 0; dnt < 8; dnt++) {
                uint32_t vh[2], vl[2];
                uint2 a = *(const uint2*)(smf + FA_VH + (size_t)(((dnt * 8 + kt) * 32 + lane) * 2) * 4);
                vh[0] = a.x; vh[1] = a.y;
                uint2 c = *(const uint2*)(smf + FA_VL + (size_t)(((dnt * 8 + kt) * 32 + lane) * 2) * 4);
                vl[0] = c.x; vl[1] = c.y;
                mma_bf16(o[dnt], ph, vh);
                mma_bf16(o[dnt], ph, vl);
                mma_bf16(o[dnt], pl, vh);
            }
        }
        ls0 += __shfl_xor_sync(0xffffffffu, ls0, 1);
        ls0 += __shfl_xor_sync(0xffffffffu, ls0, 2);
        ls1 += __shfl_xor_sync(0xffffffffu, ls1, 1);
        ls1 += __shfl_xor_sync(0xffffffffu, ls1, 2);
        l0 = l0 * al0 + ls0;
        l1 = l1 * al1 + ls1;
    }

    // ---- packed epilogue ----
    __syncthreads();
    uint32_t* sh = (uint32_t*)(smf + FA_KH);
    uint32_t* sl = (uint32_t*)(smf + FA_KL);
    float inv0 = 1.0f / l0, inv1 = 1.0f / l1;
    #pragma unroll
    for (int dnt = 0; dnt < 8; dnt++) {
        int kl_ = dnt * 8 + 2 * t;
        int ktl = kl_ >> 4;
        int rk = dnt & 1;
        int baseI = ((warp * 4 + ktl) * 32 + lane) * 4;
        uint32_t ph, pl;
        split_pack(o[dnt][0] * inv0, o[dnt][1] * inv0, ph, pl);
        sh[baseI + 2 * rk] = ph; sl[baseI + 2 * rk] = pl;
        split_pack(o[dnt][2] * inv1, o[dnt][3] * inv1, ph, pl);
        sh[baseI + 1 + 2 * rk] = ph; sl[baseI + 1 + 2 * rk] = pl;
    }
    __syncthreads();
    #pragma unroll
    for (int q = 0; q < 4; q++) {
        int i = q * 256 + tid;
        int mtl = i >> 7, jj = i & 127;
        size_t gidx = (((size_t)(b * 32 + blockIdx.x * 8 + mtl) * 64) + h * 4) * 128 + (size_t)jj * 4;
        *(uint4*)(Ohi + gidx) = ((const uint4*)sh)[i];
        *(uint4*)(Olo + gidx) = ((const uint4*)sl)[i];
    }
}

// ======================= host orchestration =======================
struct Weights {
    const float *n1g, *n1b, *n2g, *n2b, *pw, *pb, *w1, *b1, *w2, *b2;
};
struct Bufs {
    float *zb; float2 *st;
    uint32_t *obh, *obl, *n2h, *n2l, *hbh, *hbl;
    uint32_t *pwh, *pwl, *w1h, *w1l, *w2h, *w2l;
};

// One full transformer block over the batched 4096-row stream.
static void block_batched(float* resbuf, float* outbuf, int kvxor,
                          const Bufs& B, const Weights& W, const int* guard) {
    ln_stats<<<R2_ / 8, 256>>>(resbuf, B.st, guard);
    fattn_kernel<<<dim3(4, 8 * NH_), 256, FA_SMEM>>>(
        resbuf, B.st, W.n1g, W.n1b, kvxor, B.obh, B.obl, guard);
    gemm_mma<1><<<dim3(C_ / 128, R2_ / 128), 256, GM_SMEM>>>(
        B.obh, B.obl, B.pwh, B.pwl, outbuf, W.pb, resbuf, nullptr, nullptr,
        R2_, C_, C_, guard);
    lnp_kernel<<<R2_ / 16, 256, 65536>>>(outbuf, B.n2h, B.n2l, W.n2g, W.n2b, guard);
    gemm_mma<2><<<dim3(HID_ / 128, R2_ / 128), 256, GM_SMEM>>>(
        B.n2h, B.n2l, B.w1h, B.w1l, nullptr, W.b1, nullptr, B.hbh, B.hbl,
        R2_, HID_, C_, guard);
    gemm_mma<1><<<dim3(C_ / 128, R2_ / 128), 256, GM_SMEM>>>(
        B.hbh, B.hbl, B.w2h, B.w2l, outbuf, W.b2, outbuf, nullptr, nullptr,
        R2_, C_, HID_, guard);
}

extern "C" void kernel_launch(void* const* d_in, const int* in_sizes, int n_in,
                              void* d_out, int out_size) {
    const float* x   = (const float*)d_in[0];
    const float* y   = (const float*)d_in[1];
    Weights W;
    W.n1g = (const float*)d_in[2];  W.n1b = (const float*)d_in[3];
    W.n2g = (const float*)d_in[4];  W.n2b = (const float*)d_in[5];
    W.pw  = (const float*)d_in[6];  W.pb  = (const float*)d_in[7];
    W.w1  = (const float*)d_in[8];  W.b1  = (const float*)d_in[9];
    W.w2  = (const float*)d_in[10]; W.b2  = (const float*)d_in[11];
    const int* flag = (const int*)d_in[12];
    float* out = (float*)d_out;    // 4096 x 1024 = concat(x1, y1)

    Bufs B;
    cudaGetSymbolAddress((void**)&B.zb, g_zb);
    cudaGetSymbolAddress((void**)&B.st, g_st);
    cudaGetSymbolAddress((void**)&B.obh, g_obh);
    cudaGetSymbolAddress((void**)&B.obl, g_obl);
    cudaGetSymbolAddress((void**)&B.n2h, g_n2h);
    cudaGetSymbolAddress((void**)&B.n2l, g_n2l);
    cudaGetSymbolAddress((void**)&B.hbh, g_hbh);
    cudaGetSymbolAddress((void**)&B.hbl, g_hbl);
    cudaGetSymbolAddress((void**)&B.pwh, g_pwh);
    cudaGetSymbolAddress((void**)&B.pwl, g_pwl);
    cudaGetSymbolAddress((void**)&B.w1h, g_w1h);
    cudaGetSymbolAddress((void**)&B.w1l, g_w1l);
    cudaGetSymbolAddress((void**)&B.w2h, g_w2h);
    cudaGetSymbolAddress((void**)&B.w2l, g_w2l);

    cudaFuncSetAttribute(gemm_mma<1>, cudaFuncAttributeMaxDynamicSharedMemorySize, GM_SMEM);
    cudaFuncSetAttribute(gemm_mma<2>, cudaFuncAttributeMaxDynamicSharedMemorySize, GM_SMEM);
    cudaFuncSetAttribute(fattn_kernel, cudaFuncAttributeMaxDynamicSharedMemorySize, FA_SMEM);
    cudaFuncSetAttribute(lnp_kernel, cudaFuncAttributeMaxDynamicSharedMemorySize, 65536);

    // weight prep (runs every launch; ~25us)
    pack_weight<<<512, 256>>>(W.pw, B.pwh, B.pwl, C_, C_);
    pack_weight<<<512, 256>>>(W.w1, B.w1h, B.w1l, C_, HID_);
    pack_weight<<<512, 256>>>(W.w2, B.w2h, B.w2l, HID_, C_);

    const size_t bytes = (size_t)R_ * C_ * sizeof(float);
    cudaMemcpyAsync(B.zb, x, bytes, cudaMemcpyDeviceToDevice);
    cudaMemcpyAsync(B.zb + (size_t)R_ * C_, y, bytes, cudaMemcpyDeviceToDevice);

    // x and y self-chains batched as 8 "batches" (x:0-3, y:4-7). Only the
    // FINAL iteration's cross block is live: 4 gated self blocks, then one
    // cross block (kv from opposite half).
    for (int it = 0; it < 4; it++) {
        block_batched(B.zb, B.zb, 0, B, W, flag);
    }
    block_batched(B.zb, out, 4, B, W, nullptr);
}

// round 9
// speedup vs baseline: 1.1607x; 1.0010x over previous
#include <cuda_runtime.h>
#include <cuda_bf16.h>
#include <math.h>
#include <stdint.h>

// Problem dims (fixed by the dataset)
#define B_   4
#define N_   512
#define C_   1024
#define HID_ 4096
#define NH_  16
#define D_   64
#define R_   (B_*N_)     // 2048 rows per stream
#define R2_  (2*R_)      // 4096 rows: x-stream and y-stream batched
#define EPS_ 1e-5f

// ---------------- scratch (device globals: no allocation allowed) ----------
__device__ float g_zb[R2_*C_];    // concat(x, y) residual stream
__device__ float2 g_st[R2_];      // per-row LN1 stats (mean, rstd)
// packed (hi/lo, A-fragment layout) activations
__device__ uint32_t g_obh[R2_*C_/2],  g_obl[R2_*C_/2];    // fattn out -> proj A
__device__ uint32_t g_n2h[R2_*C_/2],  g_n2l[R2_*C_/2];    // ln2 out   -> fc1 A
__device__ uint32_t g_hbh[R2_*HID_/2], g_hbl[R2_*HID_/2]; // gelu out  -> fc2 A
// hi/lo-split weights, packed in mma.m16n8k16 B-fragment layout
__device__ uint32_t g_pwh[C_*C_/2],   g_pwl[C_*C_/2];
__device__ uint32_t g_w1h[C_*HID_/2], g_w1l[C_*HID_/2];
__device__ uint32_t g_w2h[HID_*C_/2], g_w2l[HID_*C_/2];

// ======================= helpers =======================
#define CP_ASYNC16(sm, gp) \
    asm volatile("cp.async.cg.shared.global [%0], [%1], 16;" :: "r"(sm), "l"(gp))
#define CP_COMMIT() asm volatile("cp.async.commit_group;" ::: "memory")
#define CP_WAIT0()  asm volatile("cp.async.wait_group 0;" ::: "memory")
#define CP_WAIT1()  asm volatile("cp.async.wait_group 1;" ::: "memory")

__device__ __forceinline__ uint32_t smem_u32(const void* p) {
    uint32_t a;
    asm("{ .reg .u64 t; cvta.to.shared.u64 t, %1; cvt.u32.u64 %0, t; }" : "=r"(a) : "l"(p));
    return a;
}

__device__ __forceinline__ void splitbf(float x, uint16_t& h, uint16_t& l) {
    __nv_bfloat16 bh = __float2bfloat16_rn(x);
    float r = x - __bfloat162float(bh);
    __nv_bfloat16 bl = __float2bfloat16_rn(r);
    h = __bfloat16_as_ushort(bh);
    l = __bfloat16_as_ushort(bl);
}
__device__ __forceinline__ uint32_t pack2(uint16_t lo16, uint16_t hi16) {
    return (uint32_t)lo16 | ((uint32_t)hi16 << 16);
}
__device__ __forceinline__ void split_pack(float a, float b, uint32_t& ph, uint32_t& pl) {
    uint16_t ha, la, hb2, lb2;
    splitbf(a, ha, la); splitbf(b, hb2, lb2);
    ph = pack2(ha, hb2); pl = pack2(la, lb2);
}

__device__ __forceinline__ void mma_bf16(float* c, const uint32_t* a, const uint32_t* b) {
    asm volatile(
        "mma.sync.aligned.m16n8k16.row.col.f32.bf16.bf16.f32 "
        "{%0,%1,%2,%3}, {%4,%5,%6,%7}, {%8,%9}, {%0,%1,%2,%3};"
        : "+f"(c[0]), "+f"(c[1]), "+f"(c[2]), "+f"(c[3])
        : "r"(a[0]), "r"(a[1]), "r"(a[2]), "r"(a[3]), "r"(b[0]), "r"(b[1]));
}

__device__ __forceinline__ float fast_exp(float x) {
    float tt = fmaxf(x * 1.4426950408889634f, -126.0f);
    float fi = floorf(tt);
    float f = tt - fi;
    float p = 0.0013333558f;
    p = fmaf(p, f, 0.0096181291f);
    p = fmaf(p, f, 0.0555041087f);
    p = fmaf(p, f, 0.2402265070f);
    p = fmaf(p, f, 0.6931471806f);
    p = fmaf(p, f, 1.0f);
    return p * __int_as_float((__float2int_rn(fi) + 127) << 23);
}

// =============== LN1 row stats: mean + rstd only (one warp per row) =========
__global__ void __launch_bounds__(256) ln_stats(const float* __restrict__ in,
                                                float2* __restrict__ st,
                                                const int* guard) {
    if (guard && !guard[0]) return;
    int row = blockIdx.x * 8 + (threadIdx.x >> 5);
    int lane = threadIdx.x & 31;
    const float* x = in + (size_t)row * C_;
    float s = 0.f, ss = 0.f;
    #pragma unroll
    for (int i = 0; i < 8; i++) {
        float4 v = *(const float4*)(x + i * 128 + lane * 4);
        s += v.x + v.y + v.z + v.w;
        ss += v.x * v.x + v.y * v.y + v.z * v.z + v.w * v.w;
    }
    #pragma unroll
    for (int o = 16; o; o >>= 1) {
        s  += __shfl_xor_sync(0xffffffffu, s, o);
        ss += __shfl_xor_sync(0xffffffffu, ss, o);
    }
    if (lane == 0) {
        float mean = s * (1.0f / C_);
        float rstd = rsqrtf(ss * (1.0f / C_) - mean * mean + EPS_);
        st[row] = make_float2(mean, rstd);
    }
}

// ============ LayerNorm -> packed hi/lo A-fragments (for ln2 -> fc1) =========
__global__ void __launch_bounds__(256) lnp_kernel(
    const float* __restrict__ in, uint32_t* __restrict__ outH,
    uint32_t* __restrict__ outL, const float* __restrict__ gm,
    const float* __restrict__ bt, const int* guard)
{
    if (guard && !guard[0]) return;
    extern __shared__ __align__(16) char sml[];
    uint32_t* sh = (uint32_t*)sml;
    uint32_t* sl = (uint32_t*)(sml + 32768);
    const int w = threadIdx.x >> 5, lane = threadIdx.x & 31;

    #pragma unroll
    for (int rr = 0; rr < 2; rr++) {
        const int row = blockIdx.x * 16 + w * 2 + rr;
        const float* x = in + (size_t)row * C_;
        float4 v[8];
        float s = 0.f, ss = 0.f;
        #pragma unroll
        for (int i = 0; i < 8; i++) {
            v[i] = *(const float4*)(x + i * 128 + lane * 4);
            s += v[i].x + v[i].y + v[i].z + v[i].w;
            ss += v[i].x * v[i].x + v[i].y * v[i].y + v[i].z * v[i].z + v[i].w * v[i].w;
        }
        #pragma unroll
        for (int o = 16; o; o >>= 1) {
            s  += __shfl_xor_sync(0xffffffffu, s, o);
            ss += __shfl_xor_sync(0xffffffffu, ss, o);
        }
        float mean = s * (1.0f / C_);
        float rstd = rsqrtf(ss * (1.0f / C_) - mean * mean + EPS_);
        const int ag = row & 7, m8 = (row >> 3) & 1;
        const int kin = (lane & 3) * 4;
        const int tt0 = (kin & 7) >> 1, rk = kin >> 3;
        #pragma unroll
        for (int i = 0; i < 8; i++) {
            int c = i * 128 + lane * 4;
            float4 gv = *(const float4*)(gm + c);
            float4 bv = *(const float4*)(bt + c);
            float n0 = (v[i].x - mean) * rstd * gv.x + bv.x;
            float n1 = (v[i].y - mean) * rstd * gv.y + bv.y;
            float n2 = (v[i].z - mean) * rstd * gv.z + bv.z;
            float n3 = (v[i].w - mean) * rstd * gv.w + bv.w;
            int kt = c >> 4;
            int r = m8 + 2 * rk;
            uint32_t ph, pl;
            split_pack(n0, n1, ph, pl);
            int idx0 = (kt * 32 + ag * 4 + tt0) * 4 + r;
            sh[idx0] = ph; sl[idx0] = pl;
            split_pack(n2, n3, ph, pl);
            int idx1 = (kt * 32 + ag * 4 + tt0 + 1) * 4 + r;
            sh[idx1] = ph; sl[idx1] = pl;
        }
    }
    __syncthreads();
    size_t gbase = (size_t)blockIdx.x * 8192;
    #pragma unroll
    for (int q = 0; q < 8; q++) {
        int i = q * 256 + threadIdx.x;
        *(uint4*)(outH + gbase + (size_t)i * 4) = ((const uint4*)sh)[i];
        *(uint4*)(outL + gbase + (size_t)i * 4) = ((const uint4*)sl)[i];
    }
}

// ========== weight prep: hi/lo split + pack into B-fragment layout =========
__global__ void pack_weight(const float* __restrict__ W, uint32_t* __restrict__ hiP,
                            uint32_t* __restrict__ loP, int K, int N) {
    int warp = threadIdx.x >> 5, lane = threadIdx.x & 31;
    int g = lane >> 2, t = lane & 3;
    int ktiles = K >> 4;
    int tiles = (N >> 3) * ktiles;
    for (int tile = blockIdx.x * 8 + warp; tile < tiles; tile += gridDim.x * 8) {
        int ntg = tile / ktiles, ksg = tile % ktiles;
        int n = ntg * 8 + g;
        #pragma unroll
        for (int reg = 0; reg < 2; reg++) {
            int k = ksg * 16 + 2 * t + reg * 8;
            float x0 = W[(size_t)k * N + n];
            float x1 = W[(size_t)(k + 1) * N + n];
            uint16_t h0, l0, h1, l1;
            splitbf(x0, h0, l0);
            splitbf(x1, h1, l1);
            size_t idx = ((size_t)tile * 32 + lane) * 2 + reg;
            hiP[idx] = pack2(h0, h1);
            loP[idx] = pack2(l0, l1);
        }
    }
}

// ======================= bf16-split mma GEMM (packed A + packed B) ==========
// 128x128 CTA tile, K-step 32, 3-stage cp.async pipeline, 8 warps.
// Warp tile 32x64 (wm = warp&3 m-slot, wn = warp>>2 n-slot): acc[2][8][4] =
// 64 regs -> ~115 regs total, genuinely fits __launch_bounds__(256, 2) for
// 2 CTAs/SM (96KB x 2 smem) with no spills.
#define GM_STAGE 32768
#define GM_SMEM  (3 * GM_STAGE)

template <int EPI>
__global__ void __launch_bounds__(256, 2) gemm_mma(
    const uint32_t* __restrict__ AhiP, const uint32_t* __restrict__ AloP,
    const uint32_t* __restrict__ BhiP, const uint32_t* __restrict__ BloP,
    float* __restrict__ Cout, const float* __restrict__ bias,
    const float* __restrict__ res,
    uint32_t* __restrict__ OutHi, uint32_t* __restrict__ OutLo,
    int M, int Nt, int K, const int* guard)
{
    if (guard && !guard[0]) return;
    extern __shared__ __align__(16) char smc[];
    const int tid = threadIdx.x;
    const int warp = tid >> 5, lane = tid & 31;
    const int g = lane >> 2, t = lane & 3;
    const int wm = warp & 3, wn = warp >> 2;          // 4 m-slots x 2 n-slots
    const int bm = blockIdx.y * 128, bn = blockIdx.x * 128;
    const uint32_t sb = smem_u32(smc);

    const int NIT = K >> 5;
    const int ktiles = K >> 4;
    const int bm16 = bm >> 4, bn8 = bn >> 3;

    auto cpA = [&](int stage, int it) {
        uint32_t dstb = sb + stage * GM_STAGE;
        int kt0 = it * 2;
        #pragma unroll
        for (int q = 0; q < 2; q++) {
            int chunk = q * 256 + tid;
            int mtk = chunk >> 5, j = chunk & 31;
            int mtl = mtk >> 1, ktl = mtk & 1;
            size_t gidx = (((size_t)(bm16 + mtl) * ktiles + kt0 + ktl) * 32 + j) * 4;
            uint32_t dst = dstb + (uint32_t)(mtk * 512 + j * 16);
            CP_ASYNC16(dst, AhiP + gidx);
            CP_ASYNC16(dst + 8192u, AloP + gidx);
        }
    };
    auto cpB = [&](int stage, int it) {
        uint32_t dstb = sb + stage * GM_STAGE + 16384;
        int ksg0 = it * 2;
        #pragma unroll
        for (int q = 0; q < 2; q++) {
            int i = q * 256 + tid;
            int nt = i >> 5, j = i & 31;
            size_t srcoff = (((size_t)(bn8 + nt) * ktiles + ksg0) * 64 + (size_t)j * 4);
            uint32_t dst = dstb + (uint32_t)(nt * 512 + j * 16);
            CP_ASYNC16(dst, BhiP + srcoff);
            CP_ASYNC16(dst + 8192u, BloP + srcoff);
        }
    };

    float acc[2][8][4] = {};

    auto compute = [&](int stage) {
        char* base = smc + stage * GM_STAGE;
        #pragma unroll
        for (int ks = 0; ks < 2; ks++) {
            uint32_t ah[2][4], al[2][4];
            #pragma unroll
            for (int mt = 0; mt < 2; mt++) {
                uint32_t off = (uint32_t)(((wm * 2 + mt) * 2 + ks) * 32 + lane) * 16;
                uint4 v = *(const uint4*)(base + off);
                ah[mt][0] = v.x; ah[mt][1] = v.y; ah[mt][2] = v.z; ah[mt][3] = v.w;
                uint4 w = *(const uint4*)(base + 8192 + off);
                al[mt][0] = w.x; al[mt][1] = w.y; al[mt][2] = w.z; al[mt][3] = w.w;
            }
            #pragma unroll
            for (int nt = 0; nt < 8; nt++) {
                uint32_t off = 16384u + (uint32_t)(((wn * 8 + nt) * 2 + ks) * 32 + lane) * 8;
                uint32_t bh[2], bl[2];
                uint2 v = *(const uint2*)(base + off);
                bh[0] = v.x; bh[1] = v.y;
                uint2 w = *(const uint2*)(base + 8192 + off);
                bl[0] = w.x; bl[1] = w.y;
                #pragma unroll
                for (int mt = 0; mt < 2; mt++) {
                    mma_bf16(acc[mt][nt], ah[mt], bh);
                    mma_bf16(acc[mt][nt], ah[mt], bl);
                    mma_bf16(acc[mt][nt], al[mt], bh);
                }
            }
        }
    };

    cpA(0, 0); cpB(0, 0); CP_COMMIT();
    cpA(1, 1); cpB(1, 1); CP_COMMIT();

    int st = 0;
    for (int it = 0; it < NIT; it++) {
        if (it + 1 < NIT) { CP_WAIT1(); } else { CP_WAIT0(); }
        __syncthreads();
        if (it + 2 < NIT) {
            int ns = st + 2; if (ns >= 3) ns -= 3;
            cpA(ns, it + 2); cpB(ns, it + 2); CP_COMMIT();
        }
        compute(st);
        if (++st == 3) st = 0;
    }
    __syncthreads();

    if (EPI == 1) {
        #pragma unroll
        for (int mt = 0; mt < 2; mt++) {
            #pragma unroll
            for (int nt = 0; nt < 8; nt++) {
                int row0 = bm + wm * 32 + mt * 16 + g;
                int col = bn + wn * 64 + nt * 8 + t * 2;
                float2 bv = *(const float2*)&bias[col];
                float v0 = acc[mt][nt][0] + bv.x;
                float v1 = acc[mt][nt][1] + bv.y;
                float v2 = acc[mt][nt][2] + bv.x;
                float v3 = acc[mt][nt][3] + bv.y;
                size_t i0 = (size_t)row0 * Nt + col;
                size_t i1 = (size_t)(row0 + 8) * Nt + col;
                float2 r0 = *(const float2*)&res[i0];
                float2 r1 = *(const float2*)&res[i1];
                *(float2*)&Cout[i0] = make_float2(v0 + r0.x, v1 + r0.y);
                *(float2*)&Cout[i1] = make_float2(v2 + r1.x, v3 + r1.y);
            }
        }
    } else {
        uint32_t* sh = (uint32_t*)smc;
        uint32_t* sl = (uint32_t*)(smc + 32768);
        #pragma unroll
        for (int mt = 0; mt < 2; mt++) {
            #pragma unroll
            for (int nt = 0; nt < 8; nt++) {
                int kl = wn * 64 + nt * 8 + t * 2;
                float2 bv = *(const float2*)&bias[bn + kl];
                float v0 = acc[mt][nt][0] + bv.x;
                float v1 = acc[mt][nt][1] + bv.y;
                float v2 = acc[mt][nt][2] + bv.x;
                float v3 = acc[mt][nt][3] + bv.y;
                v0 = 0.5f * v0 * (1.0f + erff(v0 * 0.70710678118654752f));
                v1 = 0.5f * v1 * (1.0f + erff(v1 * 0.70710678118654752f));
                v2 = 0.5f * v2 * (1.0f + erff(v2 * 0.70710678118654752f));
                v3 = 0.5f * v3 * (1.0f + erff(v3 * 0.70710678118654752f));
                int mtl = wm * 2 + mt;               // 0..7
                int ktl = kl >> 4;
                int tt = (kl & 7) >> 1;              // == t
                int rk = (kl >> 3) & 1;
                int baseI = ((mtl * 8 + ktl) * 32 + g * 4 + tt) * 4;
                uint32_t ph, pl;
                split_pack(v0, v1, ph, pl);
                sh[baseI + 2 * rk] = ph; sl[baseI + 2 * rk] = pl;
                split_pack(v2, v3, ph, pl);
                sh[baseI + 1 + 2 * rk] = ph; sl[baseI + 1 + 2 * rk] = pl;
            }
        }
        __syncthreads();
        const int ktO = Nt >> 4;
        #pragma unroll
        for (int q = 0; q < 8; q++) {
            int i = q * 256 + tid;
            int mtl = i >> 8, jj = i & 255;
            size_t gidx = (((size_t)(bm16 + mtl) * ktO + (bn >> 4)) * 128) + (size_t)jj * 4;
            *(uint4*)(OutHi + gidx) = ((const uint4*)sh)[i];
            *(uint4*)(OutLo + gidx) = ((const uint4*)sl)[i];
        }
    }
}

// ======================= fused flash attention (LN1 fused in loads) =========
#define FA_QH 0
#define FA_QL 16384
#define FA_KH 32768
#define FA_KL 49152
#define FA_VH 65536
#define FA_VL 81920
#define FA_GB 98304
#define FA_SMEM (98304 + 512)

__global__ void __launch_bounds__(256, 1) fattn_kernel(
    const float* __restrict__ Z, const float2* __restrict__ st,
    const float* __restrict__ gm, const float* __restrict__ bt,
    int kvxor, uint32_t* __restrict__ Ohi, uint32_t* __restrict__ Olo,
    const int* guard)
{
    if (guard && !guard[0]) return;
    extern __shared__ __align__(16) char smf[];
    const int tid = threadIdx.x, lane = tid & 31, warp = tid >> 5;
    const int g = lane >> 2, t = lane & 3;
    const int bh = blockIdx.y, b = bh >> 4, h = bh & 15;
    const int bk = b ^ kvxor;
    const int n0 = blockIdx.x * 128;
    float* sg = (float*)(smf + FA_GB);        // gamma slice [64]
    float* sbv = sg + 64;                     // beta slice  [64]
    if (tid < 64) {
        sg[tid]  = gm[h * D_ + tid];
        sbv[tid] = bt[h * D_ + tid];
    }
    __syncthreads();

    // ---- Q -> A-fragments (hi/lo), LN applied, scaled by 1/8 ----
    {
        const int arow = tid >> 1, hf = tid & 1;
        const int grow = b * N_ + n0 + arow;
        const float* qp = Z + (size_t)grow * C_ + h * D_ + hf * 32;
        const float2 sq = st[grow];
        const int mtile = arow >> 4, ag = arow & 7, arm = (arow >> 3) & 1;
        #pragma unroll
        for (int q4 = 0; q4 < 8; q4++) {
            float4 v = *(const float4*)(qp + q4 * 4);
            float4 gv = *(const float4*)(sg + hf * 32 + q4 * 4);
            float4 bv = *(const float4*)(sbv + hf * 32 + q4 * 4);
            float xs[4] = {
                (fmaf((v.x - sq.x) * sq.y, gv.x, bv.x)) * 0.125f,
                (fmaf((v.y - sq.x) * sq.y, gv.y, bv.y)) * 0.125f,
                (fmaf((v.z - sq.x) * sq.y, gv.z, bv.z)) * 0.125f,
                (fmaf((v.w - sq.x) * sq.y, gv.w, bv.w)) * 0.125f };
            #pragma unroll
            for (int p = 0; p < 2; p++) {
                int d = hf * 32 + q4 * 4 + 2 * p;
                uint32_t ph, pl;
                split_pack(xs[2 * p], xs[2 * p + 1], ph, pl);
                int kt = d >> 4, kin = d & 15;
                int tt = (kin & 7) >> 1, rk = kin >> 3;
                uint32_t idx = (uint32_t)(((mtile * 4 + kt) * 32 + ag * 4 + tt) * 4 + (arm + 2 * rk));
                *(uint32_t*)(smf + FA_QH + idx * 4) = ph;
                *(uint32_t*)(smf + FA_QL + idx * 4) = pl;
            }
        }
    }
    __syncthreads();

    uint32_t qh[4][4], ql[4][4];
    #pragma unroll
    for (int kt = 0; kt < 4; kt++) {
        uint4 v = *(const uint4*)(smf + FA_QH + (size_t)(((warp * 4 + kt) * 32 + lane) * 4) * 4);
        qh[kt][0] = v.x; qh[kt][1] = v.y; qh[kt][2] = v.z; qh[kt][3] = v.w;
        uint4 w = *(const uint4*)(smf + FA_QL + (size_t)(((warp * 4 + kt) * 32 + lane) * 4) * 4);
        ql[kt][0] = w.x; ql[kt][1] = w.y; ql[kt][2] = w.z; ql[kt][3] = w.w;
    }

    float o[8][4] = {};
    float m0 = -1e30f, m1 = -1e30f, l0 = 0.f, l1 = 0.f;

    for (int ch = 0; ch < 4; ch++) {
        const int s0 = ch * 128;
        __syncthreads();
        // ---- K chunk -> B-frags (LN applied) ----
        {
            const int r = tid >> 1, hf = tid & 1;
            const int grow = bk * N_ + s0 + r;
            const float* kp = Z + (size_t)grow * C_ + h * D_ + hf * 32;
            const float2 sk = st[grow];
            const int ntile = r >> 3, kg = r & 7;
            #pragma unroll
            for (int q4 = 0; q4 < 8; q4++) {
                float4 v = *(const float4*)(kp + q4 * 4);
                float4 gv = *(const float4*)(sg + hf * 32 + q4 * 4);
                float4 bv = *(const float4*)(sbv + hf * 32 + q4 * 4);
                float xs[4] = {
                    fmaf((v.x - sk.x) * sk.y, gv.x, bv.x),
                    fmaf((v.y - sk.x) * sk.y, gv.y, bv.y),
                    fmaf((v.z - sk.x) * sk.y, gv.z, bv.z),
                    fmaf((v.w - sk.x) * sk.y, gv.w, bv.w) };
                #pragma unroll
                for (int p = 0; p < 2; p++) {
                    int d = hf * 32 + q4 * 4 + 2 * p;
                    uint32_t ph, pl;
                    split_pack(xs[2 * p], xs[2 * p + 1], ph, pl);
                    int kt = d >> 4;
                    int lanef = kg * 4 + ((d & 7) >> 1);
                    int reg = ((d & 15) >= 8) ? 1 : 0;
                    uint32_t idx = (uint32_t)(((ntile * 4 + kt) * 32 + lanef) * 2 + reg);
                    *(uint32_t*)(smf + FA_KH + idx * 4) = ph;
                    *(uint32_t*)(smf + FA_KL + idx * 4) = pl;
                }
            }
        }
        // ---- V chunk -> B-frags (n=d, k=s; LN applied, float4 gamma/beta) ----
        {
            const int sp = tid & 63, dq = tid >> 6;
            const int grow = bk * N_ + s0 + 2 * sp;
            const float* vp = Z + (size_t)grow * C_ + h * D_ + dq * 16;
            const float2 sa = st[grow];
            const float2 sc = st[grow + 1];
            #pragma unroll
            for (int q4 = 0; q4 < 4; q4++) {
                float4 a = *(const float4*)(vp + q4 * 4);
                float4 c = *(const float4*)(vp + C_ + q4 * 4);
                float4 gv = *(const float4*)(sg + dq * 16 + q4 * 4);
                float4 bv = *(const float4*)(sbv + dq * 16 + q4 * 4);
                float as[4] = {
                    fmaf((a.x - sa.x) * sa.y, gv.x, bv.x),
                    fmaf((a.y - sa.x) * sa.y, gv.y, bv.y),
                    fmaf((a.z - sa.x) * sa.y, gv.z, bv.z),
                    fmaf((a.w - sa.x) * sa.y, gv.w, bv.w) };
                float cs[4] = {
                    fmaf((c.x - sc.x) * sc.y, gv.x, bv.x),
                    fmaf((c.y - sc.x) * sc.y, gv.y, bv.y),
                    fmaf((c.z - sc.x) * sc.y, gv.z, bv.z),
                    fmaf((c.w - sc.x) * sc.y, gv.w, bv.w) };
                #pragma unroll
                for (int e = 0; e < 4; e++) {
                    int d = dq * 16 + q4 * 4 + e;
                    uint32_t ph, pl;
                    split_pack(as[e], cs[e], ph, pl);
                    int dnt = d >> 3, skt = sp >> 3;
                    int lanef = (d & 7) * 4 + (sp & 3);
                    int reg = (sp >> 2) & 1;
                    uint32_t idx = (uint32_t)(((dnt * 8 + skt) * 32 + lanef) * 2 + reg);
                    *(uint32_t*)(smf + FA_VH + idx * 4) = ph;
                    *(uint32_t*)(smf + FA_VL + idx * 4) = pl;
                }
            }
        }
        __syncthreads();

        // ---- S = Q @ K^T (3-term) ----
        float s[16][4];
        #pragma unroll
        for (int nt = 0; nt < 16; nt++) { s[nt][0] = s[nt][1] = s[nt][2] = s[nt][3] = 0.f; }
        #pragma unroll
        for (int nt = 0; nt < 16; nt++) {
            #pragma unroll
            for (int kt = 0; kt < 4; kt++) {
                uint32_t kh[2], kl[2];
                uint2 a = *(const uint2*)(smf + FA_KH + (size_t)(((nt * 4 + kt) * 32 + lane) * 2) * 4);
                kh[0] = a.x; kh[1] = a.y;
                uint2 c = *(const uint2*)(smf + FA_KL + (size_t)(((nt * 4 + kt) * 32 + lane) * 2) * 4);
                kl[0] = c.x; kl[1] = c.y;
                mma_bf16(s[nt], qh[kt], kh);
                mma_bf16(s[nt], qh[kt], kl);
                mma_bf16(s[nt], ql[kt], kh);
            }
        }

        // ---- online softmax ----
        float cm0 = -1e30f, cm1 = -1e30f;
        #pragma unroll
        for (int nt = 0; nt < 16; nt++) {
            cm0 = fmaxf(cm0, fmaxf(s[nt][0], s[nt][1]));
            cm1 = fmaxf(cm1, fmaxf(s[nt][2], s[nt][3]));
        }
        cm0 = fmaxf(cm0, __shfl_xor_sync(0xffffffffu, cm0, 1));
        cm0 = fmaxf(cm0, __shfl_xor_sync(0xffffffffu, cm0, 2));
        cm1 = fmaxf(cm1, __shfl_xor_sync(0xffffffffu, cm1, 1));
        cm1 = fmaxf(cm1, __shfl_xor_sync(0xffffffffu, cm1, 2));
        float nm0 = fmaxf(m0, cm0), nm1 = fmaxf(m1, cm1);
        float al0 = fast_exp(m0 - nm0), al1 = fast_exp(m1 - nm1);
        m0 = nm0; m1 = nm1;
        #pragma unroll
        for (int dnt = 0; dnt < 8; dnt++) {
            o[dnt][0] *= al0; o[dnt][1] *= al0;
            o[dnt][2] *= al1; o[dnt][3] *= al1;
        }
        float ls0 = 0.f, ls1 = 0.f;

        #pragma unroll
        for (int kt = 0; kt < 8; kt++) {
            float p00 = fast_exp(s[2 * kt][0] - m0);
            float p01 = fast_exp(s[2 * kt][1] - m0);
            float p02 = fast_exp(s[2 * kt][2] - m1);
            float p03 = fast_exp(s[2 * kt][3] - m1);
            float p10 = fast_exp(s[2 * kt + 1][0] - m0);
            float p11 = fast_exp(s[2 * kt + 1][1] - m0);
            float p12 = fast_exp(s[2 * kt + 1][2] - m1);
            float p13 = fast_exp(s[2 * kt + 1][3] - m1);
            ls0 += p00 + p01 + p10 + p11;
            ls1 += p02 + p03 + p12 + p13;
            uint32_t ph[4], pl[4];
            split_pack(p00, p01, ph[0], pl[0]);
            split_pack(p02, p03, ph[1], pl[1]);
            split_pack(p10, p11, ph[2], pl[2]);
            split_pack(p12, p13, ph[3], pl[3]);
            #pragma unroll
            for (int dnt = 0; dnt < 8; dnt++) {
                uint32_t vh[2], vl[2];
                uint2 a = *(const uint2*)(smf + FA_VH + (size_t)(((dnt * 8 + kt) * 32 + lane) * 2) * 4);
                vh[0] = a.x; vh[1] = a.y;
                uint2 c = *(const uint2*)(smf + FA_VL + (size_t)(((dnt * 8 + kt) * 32 + lane) * 2) * 4);
                vl[0] = c.x; vl[1] = c.y;
                mma_bf16(o[dnt], ph, vh);
                mma_bf16(o[dnt], ph, vl);
                mma_bf16(o[dnt], pl, vh);
            }
        }
        ls0 += __shfl_xor_sync(0xffffffffu, ls0, 1);
        ls0 += __shfl_xor_sync(0xffffffffu, ls0, 2);
        ls1 += __shfl_xor_sync(0xffffffffu, ls1, 1);
        ls1 += __shfl_xor_sync(0xffffffffu, ls1, 2);
        l0 = l0 * al0 + ls0;
        l1 = l1 * al1 + ls1;
    }

    // ---- packed epilogue ----
    __syncthreads();
    uint32_t* sh = (uint32_t*)(smf + FA_KH);
    uint32_t* sl = (uint32_t*)(smf + FA_KL);
    float inv0 = 1.0f / l0, inv1 = 1.0f / l1;
    #pragma unroll
    for (int dnt = 0; dnt < 8; dnt++) {
        int kl_ = dnt * 8 + 2 * t;
        int ktl = kl_ >> 4;
        int rk = dnt & 1;
        int baseI = ((warp * 4 + ktl) * 32 + lane) * 4;
        uint32_t ph, pl;
        split_pack(o[dnt][0] * inv0, o[dnt][1] * inv0, ph, pl);
        sh[baseI + 2 * rk] = ph; sl[baseI + 2 * rk] = pl;
        split_pack(o[dnt][2] * inv1, o[dnt][3] * inv1, ph, pl);
        sh[baseI + 1 + 2 * rk] = ph; sl[baseI + 1 + 2 * rk] = pl;
    }
    __syncthreads();
    #pragma unroll
    for (int q = 0; q < 4; q++) {
        int i = q * 256 + tid;
        int mtl = i >> 7, jj = i & 127;
        size_t gidx = (((size_t)(b * 32 + blockIdx.x * 8 + mtl) * 64) + h * 4) * 128 + (size_t)jj * 4;
        *(uint4*)(Ohi + gidx) = ((const uint4*)sh)[i];
        *(uint4*)(Olo + gidx) = ((const uint4*)sl)[i];
    }
}

// ======================= host orchestration =======================
struct Weights {
    const float *n1g, *n1b, *n2g, *n2b, *pw, *pb, *w1, *b1, *w2, *b2;
};
struct Bufs {
    float *zb; float2 *st;
    uint32_t *obh, *obl, *n2h, *n2l, *hbh, *hbl;
    uint32_t *pwh, *pwl, *w1h, *w1l, *w2h, *w2l;
};

// One full transformer block over the batched 4096-row stream.
static void block_batched(float* resbuf, float* outbuf, int kvxor,
                          const Bufs& B, const Weights& W, const int* guard) {
    ln_stats<<<R2_ / 8, 256>>>(resbuf, B.st, guard);
    fattn_kernel<<<dim3(4, 8 * NH_), 256, FA_SMEM>>>(
        resbuf, B.st, W.n1g, W.n1b, kvxor, B.obh, B.obl, guard);
    gemm_mma<1><<<dim3(C_ / 128, R2_ / 128), 256, GM_SMEM>>>(
        B.obh, B.obl, B.pwh, B.pwl, outbuf, W.pb, resbuf, nullptr, nullptr,
        R2_, C_, C_, guard);
    lnp_kernel<<<R2_ / 16, 256, 65536>>>(outbuf, B.n2h, B.n2l, W.n2g, W.n2b, guard);
    gemm_mma<2><<<dim3(HID_ / 128, R2_ / 128), 256, GM_SMEM>>>(
        B.n2h, B.n2l, B.w1h, B.w1l, nullptr, W.b1, nullptr, B.hbh, B.hbl,
        R2_, HID_, C_, guard);
    gemm_mma<1><<<dim3(C_ / 128, R2_ / 128), 256, GM_SMEM>>>(
        B.hbh, B.hbl, B.w2h, B.w2l, outbuf, W.b2, outbuf, nullptr, nullptr,
        R2_, C_, HID_, guard);
}

extern "C" void kernel_launch(void* const* d_in, const int* in_sizes, int n_in,
                              void* d_out, int out_size) {
    const float* x   = (const float*)d_in[0];
    const float* y   = (const float*)d_in[1];
    Weights W;
    W.n1g = (const float*)d_in[2];  W.n1b = (const float*)d_in[3];
    W.n2g = (const float*)d_in[4];  W.n2b = (const float*)d_in[5];
    W.pw  = (const float*)d_in[6];  W.pb  = (const float*)d_in[7];
    W.w1  = (const float*)d_in[8];  W.b1  = (const float*)d_in[9];
    W.w2  = (const float*)d_in[10]; W.b2  = (const float*)d_in[11];
    const int* flag = (const int*)d_in[12];
    float* out = (float*)d_out;    // 4096 x 1024 = concat(x1, y1)

    Bufs B;
    cudaGetSymbolAddress((void**)&B.zb, g_zb);
    cudaGetSymbolAddress((void**)&B.st, g_st);
    cudaGetSymbolAddress((void**)&B.obh, g_obh);
    cudaGetSymbolAddress((void**)&B.obl, g_obl);
    cudaGetSymbolAddress((void**)&B.n2h, g_n2h);
    cudaGetSymbolAddress((void**)&B.n2l, g_n2l);
    cudaGetSymbolAddress((void**)&B.hbh, g_hbh);
    cudaGetSymbolAddress((void**)&B.hbl, g_hbl);
    cudaGetSymbolAddress((void**)&B.pwh, g_pwh);
    cudaGetSymbolAddress((void**)&B.pwl, g_pwl);
    cudaGetSymbolAddress((void**)&B.w1h, g_w1h);
    cudaGetSymbolAddress((void**)&B.w1l, g_w1l);
    cudaGetSymbolAddress((void**)&B.w2h, g_w2h);
    cudaGetSymbolAddress((void**)&B.w2l, g_w2l);

    cudaFuncSetAttribute(gemm_mma<1>, cudaFuncAttributeMaxDynamicSharedMemorySize, GM_SMEM);
    cudaFuncSetAttribute(gemm_mma<2>, cudaFuncAttributeMaxDynamicSharedMemorySize, GM_SMEM);
    cudaFuncSetAttribute(fattn_kernel, cudaFuncAttributeMaxDynamicSharedMemorySize, FA_SMEM);
    cudaFuncSetAttribute(lnp_kernel, cudaFuncAttributeMaxDynamicSharedMemorySize, 65536);

    // weight prep (runs every launch; ~25us)
    pack_weight<<<512, 256>>>(W.pw, B.pwh, B.pwl, C_, C_);
    pack_weight<<<512, 256>>>(W.w1, B.w1h, B.w1l, C_, HID_);
    pack_weight<<<512, 256>>>(W.w2, B.w2h, B.w2l, HID_, C_);

    const size_t bytes = (size_t)R_ * C_ * sizeof(float);
    cudaMemcpyAsync(B.zb, x, bytes, cudaMemcpyDeviceToDevice);
    cudaMemcpyAsync(B.zb + (size_t)R_ * C_, y, bytes, cudaMemcpyDeviceToDevice);

    // x and y self-chains batched as 8 "batches" (x:0-3, y:4-7). Only the
    // FINAL iteration's cross block is live: 4 gated self blocks, then one
    // cross block (kv from opposite half).
    for (int it = 0; it < 4; it++) {
        block_batched(B.zb, B.zb, 0, B, W, flag);
    }
    block_batched(B.zb, out, 4, B, W, nullptr);
}